// round 12
// baseline (speedup 1.0000x reference)
#include <cuda_runtime.h>

// Problem constants
#define BATCH 16
#define SEQ   720
#define CIN   321
#define NORD  64
#define PRED  720
#define M_TOT (BATCH*CIN)        // 5136
#define MPAD  5376               // 42*128 = 84*64
#define TSPLIT 12
#define TCHUNK 60                // 720/12
#define KCH   20                 // k-chunk in gemm1 (3 per TCHUNK)
#define ROW_STRIDE (SEQ*CIN)     // 231120
#define TSTRIDE 68               // padded transpose stride (floats)
#define NCHAIN 32                // chains in buildk (A^32 stride)
#define OSTR  67                 // epilogue staging stride (2-way max)

typedef unsigned long long ull;

// ---------------- packed f32x2 helpers ----------------
__device__ __forceinline__ ull fma2(ull a, ull b, ull c) {
    ull d;
    asm("fma.rn.f32x2 %0, %1, %2, %3;" : "=l"(d) : "l"(a), "l"(b), "l"(c));
    return d;
}
__device__ __forceinline__ ull dup2(float x) {
    ull d; asm("mov.b64 %0, {%1, %1};" : "=l"(d) : "f"(x)); return d;
}
__device__ __forceinline__ float2 upk2(ull v) {
    float x, y; asm("mov.b64 {%0, %1}, %2;" : "=f"(x), "=f"(y) : "l"(v));
    return make_float2(x, y);
}

// ---------------- device scratch ----------------
__device__ float g_Kt   [PRED*NORD];        // Kt[t][n] = (A^(719-t) B)[n]
__device__ float g_Spart[NCHAIN*NORD];
__device__ float g_EWT  [NORD*PRED];        // (E @ W) transposed: [n][p]
__device__ float g_eb   [PRED];             // E @ b_mlp
__device__ float g_XK   [TSPLIT][MPAD*NORD];
__device__ float g_XKpT [NORD*MPAD];        // alpha-folded GEMM2 operand, [n][m]
__device__ float g_rsum [TSPLIT][MPAD];
__device__ float g_rsq  [TSPLIT][MPAD];
__device__ float g_mean [MPAD];
__device__ float g_std  [MPAD];

// ============================================================================
// buildk: blocks 0..31: A^2..A^32 powers (redundant per block), seed A^r B,
// 23-step chain with A^32. Blocks 32..47: EWT = (E@W)^T and eb = E@b.
// ============================================================================
__global__ void __launch_bounds__(256) buildk_kernel(
    const float* __restrict__ A, const float* __restrict__ Bv,
    const float* __restrict__ E, const float* __restrict__ W,
    const float* __restrict__ bm)
{
    extern __shared__ float sh[];
    const int tid = threadIdx.x;
    const int bid = blockIdx.x;

    if (bid >= NCHAIN) {
        float* Wsh = sh;               // 4096
        float* Esh = sh + 4096;        // 45*64
        __shared__ float bsh[NORD];
        const int e = bid - NCHAIN;
        for (int i = tid; i < NORD*NORD; i += 256) Wsh[i] = W[i];
        for (int i = tid; i < 45*NORD; i += 256)  Esh[i] = E[e*45*NORD + i];
        if (tid < NORD) bsh[tid] = bm[tid];
        __syncthreads();
        for (int idx = tid; idx < 45*NORD; idx += 256) {
            const int pl = idx >> 6, m = idx & 63;
            float a0 = 0.f, a1 = 0.f;
#pragma unroll
            for (int n = 0; n < NORD; n += 2) {
                a0 += Esh[pl*NORD + n    ] * Wsh[(n    )*NORD + m];
                a1 += Esh[pl*NORD + n + 1] * Wsh[(n + 1)*NORD + m];
            }
            g_EWT[(size_t)m*PRED + e*45 + pl] = a0 + a1;
        }
        if (tid < 45) {
            float a = 0.f;
#pragma unroll
            for (int n = 0; n < NORD; n++) a += Esh[tid*NORD + n] * bsh[n];
            g_eb[e*45 + tid] = a;
        }
        return;
    }

    float* TP[6];
#pragma unroll
    for (int i = 0; i < 6; i++) TP[i] = sh + i * NORD * TSTRIDE;
    float* N0 = sh + 6 * NORD * TSTRIDE;
    float* N1 = N0 + NORD*NORD;
    __shared__ float vsh[NORD];
    __shared__ float pb[256];

    for (int i = tid; i < NORD*NORD; i += 256) N0[i] = A[i];
    __syncthreads();
    for (int i = tid; i < NORD*NORD; i += 256)
        TP[0][(i & 63)*TSTRIDE + (i >> 6)] = N0[i];
    __syncthreads();

    float* srcN = N0;
    float* dstN = N1;
    const int ig = tid >> 4;
    const int jg = tid & 15;
#pragma unroll
    for (int s = 0; s < 5; s++) {
        const float* srcT = TP[s];
        ull acc2[4][2];
#pragma unroll
        for (int ii = 0; ii < 4; ii++) { acc2[ii][0] = 0ull; acc2[ii][1] = 0ull; }
#pragma unroll 8
        for (int k = 0; k < NORD; k++) {
            const float4 a = *(const float4*)&srcT[k*TSTRIDE + ig*4];
            const ulonglong2 b = *(const ulonglong2*)&srcN[k*NORD + jg*4];
            float av[4] = {a.x, a.y, a.z, a.w};
#pragma unroll
            for (int ii = 0; ii < 4; ii++) {
                const ull am = dup2(av[ii]);
                acc2[ii][0] = fma2(am, b.x, acc2[ii][0]);
                acc2[ii][1] = fma2(am, b.y, acc2[ii][1]);
            }
        }
#pragma unroll
        for (int ii = 0; ii < 4; ii++) {
            const float2 lo = upk2(acc2[ii][0]);
            const float2 hi = upk2(acc2[ii][1]);
            float4 v; v.x = lo.x; v.y = lo.y; v.z = hi.x; v.w = hi.y;
            *(float4*)&dstN[(ig*4 + ii)*NORD + jg*4] = v;
        }
        __syncthreads();
        for (int i = tid; i < NORD*NORD; i += 256)
            TP[s+1][(i & 63)*TSTRIDE + (i >> 6)] = dstN[i];
        __syncthreads();
        float* tmp = srcN; srcN = dstN; dstN = tmp;
    }

    const int r = bid;
    const int n = tid & 63, q = tid >> 6;

    if (tid < NORD) vsh[tid] = Bv[tid];
    __syncthreads();
#pragma unroll
    for (int b = 0; b < 5; b++) {
        if ((r >> b) & 1) {
            float p = 0.f;
#pragma unroll
            for (int kk = 0; kk < 16; kk++) {
                const int k = q*16 + kk;
                p += TP[b][k*TSTRIDE + n] * vsh[k];
            }
            pb[tid] = p;
            __syncthreads();
            if (tid < NORD) vsh[tid] = pb[tid] + pb[tid+64] + pb[tid+128] + pb[tid+192];
            __syncthreads();
        }
    }

    const float* T32 = TP[5];
    float sacc = 0.f;
    for (int j = 0; j < 23; j++) {
        const int s_exp = 32*j + r;
        if (s_exp < 720 && tid < NORD) {
            const float u = vsh[tid];
            g_Kt[(719 - s_exp)*NORD + tid] = u;
            sacc += u;
        }
        if (j < 22) {
            float p = 0.f;
#pragma unroll
            for (int kk = 0; kk < 16; kk++) {
                const int k = q*16 + kk;
                p += T32[k*TSTRIDE + n] * vsh[k];
            }
            pb[tid] = p;
            __syncthreads();
            if (tid < NORD) vsh[tid] = pb[tid] + pb[tid+64] + pb[tid+128] + pb[tid+192];
            __syncthreads();
        }
    }
    if (tid < NORD) g_Spart[r*NORD + tid] = sacc;
}

// ============================================================================
// GEMM1: XK[m,n] = sum_t x[m,t] * Kt[t,n], fused mean/var partials.
// grid (42, 12), block 128. Mtile=128, N=64. Per thread 8m x 8n (4 m-pairs).
// b-operand staged PRE-DUPLICATED (Ks2, f32x2 pairs) -> no dup movs in loop.
// Inner loop: 6 LDS.128 + 32 FFMA2 per warp-k, conflict-free, pipelined.
// ============================================================================
__global__ void __launch_bounds__(128, 4) gemm1_kernel(const float* __restrict__ x) {
    __shared__ __align__(16) float Xs[KCH][128];    // 10 KB
    __shared__ __align__(16) ull   Ks2[KCH*64];     // 10 KB (dup'd Kt pairs)

    const int tid   = threadIdx.x;
    const int mbase = blockIdx.x * 128;
    const int h     = blockIdx.y;
    const int t0    = h * TCHUNK;

    const int m_load = mbase + tid;
    const int bidx   = m_load / CIN;
    const int chl    = m_load - bidx * CIN;
    const float* xrow = x + (size_t)bidx * ROW_STRIDE + chl;
    const bool mval   = (m_load < M_TOT);

    const int tm = tid >> 3;     // 0..15 -> m = mbase + tm*8 + 0..7
    const int tn = tid & 7;      // n = tn*4 + {0..3} and {32..35}
    const int tm8 = tm * 8;

    ull acc[4][8];               // [m-pair][nj]
#pragma unroll
    for (int i = 0; i < 4; i++)
#pragma unroll
        for (int j = 0; j < 8; j++) acc[i][j] = 0ull;
    float psum = 0.f, psq = 0.f;

    for (int kt = 0; kt < TCHUNK/KCH; kt++) {
        const int tb = t0 + kt*KCH;
#pragma unroll
        for (int tt = 0; tt < KCH; tt++) {
            float xv = mval ? xrow[(size_t)(tb + tt) * CIN] : 0.f;
            Xs[tt][tid] = xv;
            psum += xv;
            psq  += xv * xv;
        }
        // stage Ks2: pre-duplicated pairs, section layout [j*16 + tn*2]
#pragma unroll
        for (int i = 0; i < (KCH*32)/128; i++) {     // 5
            const int idx2 = tid + i*128;            // 0..639
            const int tt  = idx2 >> 5;               // 0..19
            const int u2  = idx2 & 31;
            const int j   = u2 >> 3, tnn = u2 & 7;
            const int n   = tnn*4 + ((j < 2) ? 2*j : (32 + 2*(j - 2)));
            const float2 v = *(const float2*)&g_Kt[(tb + tt)*NORD + n];
            ulonglong2 w; w.x = dup2(v.x); w.y = dup2(v.y);
            *(ulonglong2*)&Ks2[tt*64 + u2*2] = w;
        }
        __syncthreads();

        // software-pipelined inner loop (no dup movs)
        ulonglong2 A0 = *(const ulonglong2*)&Xs[0][tm8];
        ulonglong2 A1 = *(const ulonglong2*)&Xs[0][tm8 + 4];
        ulonglong2 B0 = *(const ulonglong2*)&Ks2[tn*2];
        ulonglong2 B1 = *(const ulonglong2*)&Ks2[16 + tn*2];
        ulonglong2 B2 = *(const ulonglong2*)&Ks2[32 + tn*2];
        ulonglong2 B3 = *(const ulonglong2*)&Ks2[48 + tn*2];
#pragma unroll 5
        for (int tt = 0; tt < KCH; tt++) {
            const int tnx = (tt + 1 < KCH) ? tt + 1 : 0;
            const ulonglong2 nA0 = *(const ulonglong2*)&Xs[tnx][tm8];
            const ulonglong2 nA1 = *(const ulonglong2*)&Xs[tnx][tm8 + 4];
            const ulonglong2 nB0 = *(const ulonglong2*)&Ks2[tnx*64 + tn*2];
            const ulonglong2 nB1 = *(const ulonglong2*)&Ks2[tnx*64 + 16 + tn*2];
            const ulonglong2 nB2 = *(const ulonglong2*)&Ks2[tnx*64 + 32 + tn*2];
            const ulonglong2 nB3 = *(const ulonglong2*)&Ks2[tnx*64 + 48 + tn*2];
            const ull ap[4] = {A0.x, A0.y, A1.x, A1.y};
            const ull bd[8] = {B0.x, B0.y, B1.x, B1.y, B2.x, B2.y, B3.x, B3.y};
#pragma unroll
            for (int mp = 0; mp < 4; mp++)
#pragma unroll
                for (int nj = 0; nj < 8; nj++)
                    acc[mp][nj] = fma2(ap[mp], bd[nj], acc[mp][nj]);
            A0 = nA0; A1 = nA1; B0 = nB0; B1 = nB1; B2 = nB2; B3 = nB3;
        }
        __syncthreads();
    }

    const int tn4 = tn * 4;
    float* xk = g_XK[h];
#pragma unroll
    for (int mp = 0; mp < 4; mp++) {
        const int m0 = mbase + tm8 + mp*2;
        float2 c[8];
#pragma unroll
        for (int nj = 0; nj < 8; nj++) c[nj] = upk2(acc[mp][nj]);
        float4 lo0; lo0.x = c[0].x; lo0.y = c[1].x; lo0.z = c[2].x; lo0.w = c[3].x;
        float4 lo1; lo1.x = c[4].x; lo1.y = c[5].x; lo1.z = c[6].x; lo1.w = c[7].x;
        float4 hi0; hi0.x = c[0].y; hi0.y = c[1].y; hi0.z = c[2].y; hi0.w = c[3].y;
        float4 hi1; hi1.x = c[4].y; hi1.y = c[5].y; hi1.z = c[6].y; hi1.w = c[7].y;
        *(float4*)&xk[(size_t)m0 * NORD + tn4]          = lo0;
        *(float4*)&xk[(size_t)m0 * NORD + tn4 + 32]     = lo1;
        *(float4*)&xk[(size_t)(m0+1) * NORD + tn4]      = hi0;
        *(float4*)&xk[(size_t)(m0+1) * NORD + tn4 + 32] = hi1;
    }
    g_rsum[h][m_load] = psum;
    g_rsq [h][m_load] = psq;
}

// ============================================================================
// fuse: reduce t-split partials + stats + S + alpha/beta fold + transpose.
// XKpT[n, m] = alpha_m * sum_h XK[h][m,n] + beta_m * S[n]
// grid MPAD/64, block 256.
// ============================================================================
__global__ void __launch_bounds__(256) fuse_kernel(const float* __restrict__ aw,
                                                   const float* __restrict__ ab) {
    __shared__ float TT[64*65];
    __shared__ float alpha_s[64], beta_s[64], Ssh[64];
    const int tid = threadIdx.x;
    const int mb  = blockIdx.x * 64;

    if (tid < 64) {
        const int m = mb + tid;
        float s = 0.f, qq = 0.f;
#pragma unroll
        for (int h = 0; h < TSPLIT; h++) { s += g_rsum[h][m]; qq += g_rsq[h][m]; }
        const float mean = s * (1.0f / 720.0f);
        const float var  = qq * (1.0f / 720.0f) - mean * mean;
        const float sd   = sqrtf(var + 1e-5f);
        const int bidx = m / CIN;
        const int ch   = m - bidx * CIN;
        const float al = aw[ch] / sd;
        alpha_s[tid] = al;
        beta_s[tid]  = ab[ch] - mean * al;
        g_mean[m] = mean;
        g_std[m]  = sd;
    } else if (tid < 128) {
        const int nn = tid - 64;
        float s = 0.f;
#pragma unroll
        for (int rr = 0; rr < NCHAIN; rr++) s += g_Spart[rr*NORD + nn];
        Ssh[nn] = s;
    }
    __syncthreads();

#pragma unroll
    for (int i = 0; i < 16; i++) {
        const int idx = i*256 + tid;           // 0..4095
        const int ml = idx >> 6, nn = idx & 63;
        float v = 0.f;
#pragma unroll
        for (int h = 0; h < TSPLIT; h++) v += g_XK[h][(size_t)(mb + ml)*NORD + nn];
        TT[nn*65 + ml] = alpha_s[ml]*v + beta_s[ml]*Ssh[nn];
    }
    __syncthreads();
#pragma unroll
    for (int i = 0; i < 16; i++) {
        const int idx = i*256 + tid;
        const int nn = idx >> 6, ml = idx & 63;
        g_XKpT[(size_t)nn*MPAD + mb + ml] = TT[nn*65 + ml];
    }
}

// ============================================================================
// GEMM2 + epilogue: pre[m,p] = sum_n XKpT[n,m] EWT[n,p] + eb[p];
// out = (pre - ab)/(aw+1e-10)*sd + mean. Coalesced stores via smem staging.
// grid (84, 6), block 128. Mtile=64, Ptile=128. Xs full-K (16KB) + Es2
// pre-duplicated f32x2 pairs chunked 32-deep (32KB). 8m x 8p per thread.
// Inner loop: 6 LDS.128 + 32 FFMA2 per warp-k, conflict-free, pipelined.
// ============================================================================
__global__ void __launch_bounds__(128, 4) gemm2_kernel(float* __restrict__ out,
                                                       const float* __restrict__ aw,
                                                       const float* __restrict__ ab) {
    __shared__ __align__(16) float pool[12288];   // 48 KB
    float* Xs = pool;                              // [64 k][64 m] floats
    ull*  Es2 = (ull*)(pool + 4096);               // [32 k][128] dup'd pairs

    const int tid   = threadIdx.x;
    const int mbase = blockIdx.x * 64;
    const int pbase = blockIdx.y * 128;
    const int tm = tid & 7;      // m = mbase + tm*4 + {0..3, 32..35}
    const int tp = tid >> 3;     // p = pbase + tp*8 + 0..7
    const int tm4 = tm * 4;
    const int tp8 = tp * 8;

    // stage Xs (full K): 8 float4 per thread, coalesced conflict-free
#pragma unroll
    for (int i = 0; i < 8; i++) {
        const int idx = tid + i*128;            // 0..1023
        const int n = idx >> 4, mg = idx & 15;
        *(float4*)&Xs[n*64 + mg*4] =
            *(const float4*)&g_XKpT[(size_t)n*MPAD + mbase + mg*4];
    }

    ull acc[4][8];               // [m-pair][pj]
#pragma unroll
    for (int i = 0; i < 4; i++)
#pragma unroll
        for (int j = 0; j < 8; j++) acc[i][j] = 0ull;

    for (int c = 0; c < 2; c++) {
        const int nb = c * 32;
        // stage Es2: pre-duplicated pairs, section layout [j*32 + tp*2]
#pragma unroll
        for (int i = 0; i < 16; i++) {
            const int idx2 = tid + i*128;       // 0..2047
            const int k  = idx2 >> 6;           // 0..31
            const int u2 = idx2 & 63;
            const int j  = u2 >> 4, tpp = u2 & 15;
            const int pl = tpp*8 + 2*j;
            const int p  = pbase + pl;
            float2 v = make_float2(0.f, 0.f);
            if (p < PRED) v = *(const float2*)&g_EWT[(size_t)(nb + k)*PRED + p];
            ulonglong2 w; w.x = dup2(v.x); w.y = dup2(v.y);
            *(ulonglong2*)&Es2[k*128 + u2*2] = w;
        }
        __syncthreads();

        const float* Xc = Xs + nb*64;
        // software-pipelined inner loop (no dup movs)
        ulonglong2 A0 = *(const ulonglong2*)&Xc[tm4];
        ulonglong2 A1 = *(const ulonglong2*)&Xc[tm4 + 32];
        ulonglong2 B0 = *(const ulonglong2*)&Es2[tp*2];
        ulonglong2 B1 = *(const ulonglong2*)&Es2[32 + tp*2];
        ulonglong2 B2 = *(const ulonglong2*)&Es2[64 + tp*2];
        ulonglong2 B3 = *(const ulonglong2*)&Es2[96 + tp*2];
#pragma unroll 8
        for (int k = 0; k < 32; k++) {
            const int kn = (k + 1) & 31;
            const ulonglong2 nA0 = *(const ulonglong2*)&Xc[kn*64 + tm4];
            const ulonglong2 nA1 = *(const ulonglong2*)&Xc[kn*64 + tm4 + 32];
            const ulonglong2 nB0 = *(const ulonglong2*)&Es2[kn*128 + tp*2];
            const ulonglong2 nB1 = *(const ulonglong2*)&Es2[kn*128 + 32 + tp*2];
            const ulonglong2 nB2 = *(const ulonglong2*)&Es2[kn*128 + 64 + tp*2];
            const ulonglong2 nB3 = *(const ulonglong2*)&Es2[kn*128 + 96 + tp*2];
            const ull ap[4] = {A0.x, A0.y, A1.x, A1.y};
            const ull bd[8] = {B0.x, B0.y, B1.x, B1.y, B2.x, B2.y, B3.x, B3.y};
#pragma unroll
            for (int mp = 0; mp < 4; mp++)
#pragma unroll
                for (int pj = 0; pj < 8; pj++)
                    acc[mp][pj] = fma2(ap[mp], bd[pj], acc[mp][pj]);
            A0 = nA0; A1 = nA1; B0 = nB0; B1 = nB1; B2 = nB2; B3 = nB3;
        }
        __syncthreads();
    }

    // epilogue staged into Os[p_loc][m_loc] (stride OSTR=67)
    float* Os = pool;            // 128*67 = 8576 floats
    float ebv[8];
#pragma unroll
    for (int pj = 0; pj < 8; pj++) {
        const int p = pbase + tp8 + pj;
        ebv[pj] = (p < PRED) ? g_eb[p] : 0.f;
    }
#pragma unroll
    for (int mp = 0; mp < 4; mp++) {
        const int mloc0 = (mp < 2) ? (tm4 + 2*mp) : (tm4 + 32 + 2*(mp - 2));
        float2 c[8];
#pragma unroll
        for (int pj = 0; pj < 8; pj++) c[pj] = upk2(acc[mp][pj]);
#pragma unroll
        for (int w = 0; w < 2; w++) {
            const int m = mbase + mloc0 + w;
            const float mean = g_mean[m];
            const float sd   = g_std[m];
            const int bi = m / CIN;
            const int ch = m - bi * CIN;
            const float abv = ab[ch];
            const float scale = sd / (aw[ch] + 1e-10f);
#pragma unroll
            for (int pj = 0; pj < 8; pj++) {
                const float val = w ? c[pj].y : c[pj].x;
                Os[(tp8 + pj)*OSTR + mloc0 + w] = (val + ebv[pj] - abv) * scale + mean;
            }
        }
    }
    __syncthreads();

    // coalesced global store: lanes sweep m (64), two phases sweep p
    const int ml = tid & 63;
    const int ph = tid >> 6;            // 0/1
    const int m  = mbase + ml;
    if (m < M_TOT) {
        const int bi = m / CIN;
        const int ch = m - bi * CIN;
        float* ob = out + (size_t)bi * ROW_STRIDE + ch;
        const int plim = (PRED - pbase < 128) ? (PRED - pbase) : 128;
        for (int pl = ph; pl < plim; pl += 2)
            ob[(size_t)(pbase + pl) * CIN] = Os[pl*OSTR + ml];
    }
}

// ---------------- launcher: 4 graph nodes ----------------
extern "C" void kernel_launch(void* const* d_in, const int* in_sizes, int n_in,
                              void* d_out, int out_size) {
    (void)in_sizes; (void)n_in; (void)out_size;
    const float* x  = (const float*)d_in[0];   // x_enc (16,720,321)
    const float* A  = (const float*)d_in[1];   // A (64,64)
    const float* Bv = (const float*)d_in[2];   // B_vec (64)
    const float* E  = (const float*)d_in[3];   // eval_matrix (720,64)
    const float* W  = (const float*)d_in[4];   // W_mlp (64,64)
    const float* bm = (const float*)d_in[5];   // b_mlp (64)
    const float* aw = (const float*)d_in[6];   // affine_weight (321)
    const float* ab = (const float*)d_in[7];   // affine_bias (321)
    float* out = (float*)d_out;

    const int buildk_smem = (6*NORD*TSTRIDE + 2*NORD*NORD) * (int)sizeof(float); // 137216
    cudaFuncSetAttribute(buildk_kernel, cudaFuncAttributeMaxDynamicSharedMemorySize, buildk_smem);
    cudaFuncSetAttribute(gemm2_kernel, cudaFuncAttributePreferredSharedMemoryCarveout, 100);
    cudaFuncSetAttribute(gemm1_kernel, cudaFuncAttributePreferredSharedMemoryCarveout, 100);

    buildk_kernel<<<NCHAIN + 16, 256, buildk_smem>>>(A, Bv, E, W, bm);
    gemm1_kernel<<<dim3(MPAD/128, TSPLIT), 128>>>(x);
    fuse_kernel<<<MPAD/64, 256>>>(aw, ab);
    gemm2_kernel<<<dim3(MPAD/64, 6), 128>>>(out, aw, ab);
}

// round 13
// speedup vs baseline: 1.1018x; 1.1018x over previous
#include <cuda_runtime.h>

// Problem constants
#define BATCH 16
#define SEQ   720
#define CIN   321
#define NORD  64
#define PRED  720
#define M_TOT (BATCH*CIN)        // 5136
#define MPAD  5376               // 42*128 = 84*64
#define TSPLIT 12
#define TCHUNK 60                // 720/12
#define KCH   20                 // k-chunk in gemm1 (3 per TCHUNK)
#define ROW_STRIDE (SEQ*CIN)     // 231120
#define TSTRIDE 68               // padded transpose stride (floats)
#define NCHAIN 32                // chains in buildk (A^32 stride)
#define OSTR  67                 // epilogue staging stride (2-way max)

typedef unsigned long long ull;

// ---------------- packed f32x2 helpers ----------------
__device__ __forceinline__ ull fma2(ull a, ull b, ull c) {
    ull d;
    asm("fma.rn.f32x2 %0, %1, %2, %3;" : "=l"(d) : "l"(a), "l"(b), "l"(c));
    return d;
}
__device__ __forceinline__ ull dup2(float x) {
    ull d; asm("mov.b64 %0, {%1, %1};" : "=l"(d) : "f"(x)); return d;
}
__device__ __forceinline__ float2 upk2(ull v) {
    float x, y; asm("mov.b64 {%0, %1}, %2;" : "=f"(x), "=f"(y) : "l"(v));
    return make_float2(x, y);
}

// ---------------- device scratch ----------------
__device__ float g_Kt   [PRED*NORD];        // Kt[t][n] = (A^(719-t) B)[n]
__device__ float g_Spart[NCHAIN*NORD];
__device__ float g_EWT  [NORD*PRED];        // (E @ W) transposed: [n][p]
__device__ float g_eb   [PRED];             // E @ b_mlp
__device__ float g_XK   [TSPLIT][MPAD*NORD];
__device__ float g_XKpT [NORD*MPAD];        // alpha-folded GEMM2 operand, [n][m]
__device__ float g_rsum [TSPLIT][MPAD];
__device__ float g_rsq  [TSPLIT][MPAD];
__device__ float g_mean [MPAD];
__device__ float g_std  [MPAD];

// ============================================================================
// buildk: blocks 0..31: A^2..A^32 powers (redundant per block), seed A^r B,
// 23-step chain with A^32. Blocks 32..47: EWT = (E@W)^T and eb = E@b.
// ============================================================================
__global__ void __launch_bounds__(256) buildk_kernel(
    const float* __restrict__ A, const float* __restrict__ Bv,
    const float* __restrict__ E, const float* __restrict__ W,
    const float* __restrict__ bm)
{
    extern __shared__ float sh[];
    const int tid = threadIdx.x;
    const int bid = blockIdx.x;

    if (bid >= NCHAIN) {
        float* Wsh = sh;               // 4096
        float* Esh = sh + 4096;        // 45*64
        __shared__ float bsh[NORD];
        const int e = bid - NCHAIN;
        for (int i = tid; i < NORD*NORD; i += 256) Wsh[i] = W[i];
        for (int i = tid; i < 45*NORD; i += 256)  Esh[i] = E[e*45*NORD + i];
        if (tid < NORD) bsh[tid] = bm[tid];
        __syncthreads();
        for (int idx = tid; idx < 45*NORD; idx += 256) {
            const int pl = idx >> 6, m = idx & 63;
            float a0 = 0.f, a1 = 0.f;
#pragma unroll
            for (int n = 0; n < NORD; n += 2) {
                a0 += Esh[pl*NORD + n    ] * Wsh[(n    )*NORD + m];
                a1 += Esh[pl*NORD + n + 1] * Wsh[(n + 1)*NORD + m];
            }
            g_EWT[(size_t)m*PRED + e*45 + pl] = a0 + a1;
        }
        if (tid < 45) {
            float a = 0.f;
#pragma unroll
            for (int n = 0; n < NORD; n++) a += Esh[tid*NORD + n] * bsh[n];
            g_eb[e*45 + tid] = a;
        }
        return;
    }

    float* TP[6];
#pragma unroll
    for (int i = 0; i < 6; i++) TP[i] = sh + i * NORD * TSTRIDE;
    float* N0 = sh + 6 * NORD * TSTRIDE;
    float* N1 = N0 + NORD*NORD;
    __shared__ float vsh[NORD];
    __shared__ float pb[256];

    for (int i = tid; i < NORD*NORD; i += 256) N0[i] = A[i];
    __syncthreads();
    for (int i = tid; i < NORD*NORD; i += 256)
        TP[0][(i & 63)*TSTRIDE + (i >> 6)] = N0[i];
    __syncthreads();

    float* srcN = N0;
    float* dstN = N1;
    const int ig = tid >> 4;
    const int jg = tid & 15;
#pragma unroll
    for (int s = 0; s < 5; s++) {
        const float* srcT = TP[s];
        ull acc2[4][2];
#pragma unroll
        for (int ii = 0; ii < 4; ii++) { acc2[ii][0] = 0ull; acc2[ii][1] = 0ull; }
#pragma unroll 8
        for (int k = 0; k < NORD; k++) {
            const float4 a = *(const float4*)&srcT[k*TSTRIDE + ig*4];
            const ulonglong2 b = *(const ulonglong2*)&srcN[k*NORD + jg*4];
            float av[4] = {a.x, a.y, a.z, a.w};
#pragma unroll
            for (int ii = 0; ii < 4; ii++) {
                const ull am = dup2(av[ii]);
                acc2[ii][0] = fma2(am, b.x, acc2[ii][0]);
                acc2[ii][1] = fma2(am, b.y, acc2[ii][1]);
            }
        }
#pragma unroll
        for (int ii = 0; ii < 4; ii++) {
            const float2 lo = upk2(acc2[ii][0]);
            const float2 hi = upk2(acc2[ii][1]);
            float4 v; v.x = lo.x; v.y = lo.y; v.z = hi.x; v.w = hi.y;
            *(float4*)&dstN[(ig*4 + ii)*NORD + jg*4] = v;
        }
        __syncthreads();
        for (int i = tid; i < NORD*NORD; i += 256)
            TP[s+1][(i & 63)*TSTRIDE + (i >> 6)] = dstN[i];
        __syncthreads();
        float* tmp = srcN; srcN = dstN; dstN = tmp;
    }

    const int r = bid;
    const int n = tid & 63, q = tid >> 6;

    if (tid < NORD) vsh[tid] = Bv[tid];
    __syncthreads();
#pragma unroll
    for (int b = 0; b < 5; b++) {
        if ((r >> b) & 1) {
            float p = 0.f;
#pragma unroll
            for (int kk = 0; kk < 16; kk++) {
                const int k = q*16 + kk;
                p += TP[b][k*TSTRIDE + n] * vsh[k];
            }
            pb[tid] = p;
            __syncthreads();
            if (tid < NORD) vsh[tid] = pb[tid] + pb[tid+64] + pb[tid+128] + pb[tid+192];
            __syncthreads();
        }
    }

    const float* T32 = TP[5];
    float sacc = 0.f;
    for (int j = 0; j < 23; j++) {
        const int s_exp = 32*j + r;
        if (s_exp < 720 && tid < NORD) {
            const float u = vsh[tid];
            g_Kt[(719 - s_exp)*NORD + tid] = u;
            sacc += u;
        }
        if (j < 22) {
            float p = 0.f;
#pragma unroll
            for (int kk = 0; kk < 16; kk++) {
                const int k = q*16 + kk;
                p += T32[k*TSTRIDE + n] * vsh[k];
            }
            pb[tid] = p;
            __syncthreads();
            if (tid < NORD) vsh[tid] = pb[tid] + pb[tid+64] + pb[tid+128] + pb[tid+192];
            __syncthreads();
        }
    }
    if (tid < NORD) g_Spart[r*NORD + tid] = sacc;
}

// ============================================================================
// GEMM1: XK[m,n] = sum_t x[m,t] * Kt[t,n], fused mean/var partials.
// grid (42, 12), block 128. Mtile=128, N=64. Per thread 8m x 8n with the
// PAIR axis on n: acc[mi][n-pair]; b pairs load directly (no dup movs),
// only 8 a-scalars duplicated. 4 LDS.128 + 8 dup + 32 FFMA2 per warp-k.
// ============================================================================
__global__ void __launch_bounds__(128, 4) gemm1_kernel(const float* __restrict__ x) {
    __shared__ __align__(16) float Xs[KCH][128];
    __shared__ __align__(16) float Ks[KCH][64];

    const int tid   = threadIdx.x;
    const int mbase = blockIdx.x * 128;
    const int h     = blockIdx.y;
    const int t0    = h * TCHUNK;

    const int m_load = mbase + tid;
    const int bidx   = m_load / CIN;
    const int chl    = m_load - bidx * CIN;
    const float* xrow = x + (size_t)bidx * ROW_STRIDE + chl;
    const bool mval   = (m_load < M_TOT);

    const int tm = tid >> 3;     // 0..15 -> m = mbase + tm*8 + 0..7
    const int tn = tid & 7;      // n = tn*4 + {0..3} and {32..35}
    const int tm8 = tm * 8;
    const int tn4 = tn * 4;

    ull acc[8][4];               // [mi][n-pair]: pairs (n0n1),(n2n3),(n32n33),(n34n35)
#pragma unroll
    for (int i = 0; i < 8; i++)
#pragma unroll
        for (int j = 0; j < 4; j++) acc[i][j] = 0ull;
    float psum = 0.f, psq = 0.f;

    for (int kt = 0; kt < TCHUNK/KCH; kt++) {
        const int tb = t0 + kt*KCH;
#pragma unroll
        for (int tt = 0; tt < KCH; tt++) {
            float xv = mval ? xrow[(size_t)(tb + tt) * CIN] : 0.f;
            Xs[tt][tid] = xv;
            psum += xv;
            psq  += xv * xv;
        }
#pragma unroll
        for (int i = 0; i < (KCH*64)/128; i++) {
            const int idx = tid + i*128;
            const int tt = idx >> 6, nn = idx & 63;
            Ks[tt][nn] = g_Kt[(tb + tt) * NORD + nn];
        }
        __syncthreads();

        // software-pipelined inner loop: a-scalars as float4, b-pairs direct
        float4 F0 = *(const float4*)&Xs[0][tm8];
        float4 F1 = *(const float4*)&Xs[0][tm8 + 4];
        ulonglong2 K0 = *(const ulonglong2*)&Ks[0][tn4];
        ulonglong2 K1 = *(const ulonglong2*)&Ks[0][tn4 + 32];
#pragma unroll 5
        for (int tt = 0; tt < KCH; tt++) {
            const int tnx = (tt + 1 < KCH) ? tt + 1 : 0;
            const float4 nF0 = *(const float4*)&Xs[tnx][tm8];
            const float4 nF1 = *(const float4*)&Xs[tnx][tm8 + 4];
            const ulonglong2 nK0 = *(const ulonglong2*)&Ks[tnx][tn4];
            const ulonglong2 nK1 = *(const ulonglong2*)&Ks[tnx][tn4 + 32];
            const float av[8] = {F0.x, F0.y, F0.z, F0.w, F1.x, F1.y, F1.z, F1.w};
            const ull  bd[4] = {K0.x, K0.y, K1.x, K1.y};
#pragma unroll
            for (int mi = 0; mi < 8; mi++) {
                const ull am = dup2(av[mi]);
#pragma unroll
                for (int nj = 0; nj < 4; nj++)
                    acc[mi][nj] = fma2(am, bd[nj], acc[mi][nj]);
            }
            F0 = nF0; F1 = nF1; K0 = nK0; K1 = nK1;
        }
        __syncthreads();
    }

    float* xk = g_XK[h];
#pragma unroll
    for (int mi = 0; mi < 8; mi++) {
        const int m = mbase + tm8 + mi;
        const float2 c0 = upk2(acc[mi][0]);
        const float2 c1 = upk2(acc[mi][1]);
        const float2 c2 = upk2(acc[mi][2]);
        const float2 c3 = upk2(acc[mi][3]);
        float4 v0; v0.x = c0.x; v0.y = c0.y; v0.z = c1.x; v0.w = c1.y;
        float4 v1; v1.x = c2.x; v1.y = c2.y; v1.z = c3.x; v1.w = c3.y;
        *(float4*)&xk[(size_t)m * NORD + tn4]      = v0;
        *(float4*)&xk[(size_t)m * NORD + tn4 + 32] = v1;
    }
    g_rsum[h][m_load] = psum;
    g_rsq [h][m_load] = psq;
}

// ============================================================================
// fuse: reduce t-split partials + stats + S + alpha/beta fold + transpose.
// XKpT[n, m] = alpha_m * sum_h XK[h][m,n] + beta_m * S[n]
// grid MPAD/64, block 256.
// ============================================================================
__global__ void __launch_bounds__(256) fuse_kernel(const float* __restrict__ aw,
                                                   const float* __restrict__ ab) {
    __shared__ float TT[64*65];
    __shared__ float alpha_s[64], beta_s[64], Ssh[64];
    const int tid = threadIdx.x;
    const int mb  = blockIdx.x * 64;

    if (tid < 64) {
        const int m = mb + tid;
        float s = 0.f, qq = 0.f;
#pragma unroll
        for (int h = 0; h < TSPLIT; h++) { s += g_rsum[h][m]; qq += g_rsq[h][m]; }
        const float mean = s * (1.0f / 720.0f);
        const float var  = qq * (1.0f / 720.0f) - mean * mean;
        const float sd   = sqrtf(var + 1e-5f);
        const int bidx = m / CIN;
        const int ch   = m - bidx * CIN;
        const float al = aw[ch] / sd;
        alpha_s[tid] = al;
        beta_s[tid]  = ab[ch] - mean * al;
        g_mean[m] = mean;
        g_std[m]  = sd;
    } else if (tid < 128) {
        const int nn = tid - 64;
        float s = 0.f;
#pragma unroll
        for (int rr = 0; rr < NCHAIN; rr++) s += g_Spart[rr*NORD + nn];
        Ssh[nn] = s;
    }
    __syncthreads();

#pragma unroll
    for (int i = 0; i < 16; i++) {
        const int idx = i*256 + tid;           // 0..4095
        const int ml = idx >> 6, nn = idx & 63;
        float v = 0.f;
#pragma unroll
        for (int h = 0; h < TSPLIT; h++) v += g_XK[h][(size_t)(mb + ml)*NORD + nn];
        TT[nn*65 + ml] = alpha_s[ml]*v + beta_s[ml]*Ssh[nn];
    }
    __syncthreads();
#pragma unroll
    for (int i = 0; i < 16; i++) {
        const int idx = i*256 + tid;
        const int nn = idx >> 6, ml = idx & 63;
        g_XKpT[(size_t)nn*MPAD + mb + ml] = TT[nn*65 + ml];
    }
}

// ============================================================================
// GEMM2 + epilogue: pre[m,p] = sum_n XKpT[n,m] EWT[n,p] + eb[p];
// out = (pre - ab)/(aw+1e-10)*sd + mean. Coalesced stores via smem staging.
// grid (84, 6), block 128. Mtile=64, Ptile=128, K=64 resident.
// Per thread 8m x 8p with the PAIR axis on p: acc[mi][p-pair];
// 4 LDS.128 + 8 dup + 32 FFMA2 per warp-k, pipelined, conflict-free.
// ============================================================================
__global__ void __launch_bounds__(128, 4) gemm2_kernel(float* __restrict__ out,
                                                       const float* __restrict__ aw,
                                                       const float* __restrict__ ab) {
    __shared__ __align__(16) float pool[12288];   // 48 KB
    float* Xs = pool;           // [64 k][64 m]
    float* Es = pool + 4096;    // [64 k][128 p]

    const int tid   = threadIdx.x;
    const int mbase = blockIdx.x * 64;
    const int pbase = blockIdx.y * 128;
    const int tm = tid & 7;      // m = mbase + tm*4 + {0..3, 32..35}
    const int tp = tid >> 3;     // p = pbase + tp*8 + 0..7
    const int tm4 = tm * 4;
    const int tp8 = tp * 8;

    // stage Xs: 8 float4 per thread, coalesced conflict-free
#pragma unroll
    for (int i = 0; i < 8; i++) {
        const int idx = tid + i*128;            // 0..1023
        const int n = idx >> 4, mg = idx & 15;
        *(float4*)&Xs[n*64 + mg*4] =
            *(const float4*)&g_XKpT[(size_t)n*MPAD + mbase + mg*4];
    }
    // stage Es with p guard: 16 float4 per thread
#pragma unroll
    for (int i = 0; i < 16; i++) {
        const int idx = tid + i*128;            // 0..2047
        const int n = idx >> 5, pg = idx & 31;
        const int p = pbase + pg*4;
        float4 v = make_float4(0.f, 0.f, 0.f, 0.f);
        if (p < PRED) v = *(const float4*)&g_EWT[(size_t)n*PRED + p];
        *(float4*)&Es[n*128 + pg*4] = v;
    }
    __syncthreads();

    ull acc[8][4];               // [mi][p-pair]
#pragma unroll
    for (int i = 0; i < 8; i++)
#pragma unroll
        for (int j = 0; j < 4; j++) acc[i][j] = 0ull;

    // software-pipelined K loop
    float4 F0 = *(const float4*)&Xs[tm4];
    float4 F1 = *(const float4*)&Xs[tm4 + 32];
    ulonglong2 E0 = *(const ulonglong2*)&Es[tp8];
    ulonglong2 E1 = *(const ulonglong2*)&Es[tp8 + 4];
#pragma unroll 8
    for (int k = 0; k < 64; k++) {
        const int kn = (k + 1) & 63;
        const float4 nF0 = *(const float4*)&Xs[kn*64 + tm4];
        const float4 nF1 = *(const float4*)&Xs[kn*64 + tm4 + 32];
        const ulonglong2 nE0 = *(const ulonglong2*)&Es[kn*128 + tp8];
        const ulonglong2 nE1 = *(const ulonglong2*)&Es[kn*128 + tp8 + 4];
        const float av[8] = {F0.x, F0.y, F0.z, F0.w, F1.x, F1.y, F1.z, F1.w};
        const ull  bd[4] = {E0.x, E0.y, E1.x, E1.y};
#pragma unroll
        for (int mi = 0; mi < 8; mi++) {
            const ull am = dup2(av[mi]);
#pragma unroll
            for (int pj = 0; pj < 4; pj++)
                acc[mi][pj] = fma2(am, bd[pj], acc[mi][pj]);
        }
        F0 = nF0; F1 = nF1; E0 = nE0; E1 = nE1;
    }
    __syncthreads();   // done reading Xs/Es; pool reused as Os

    // epilogue staged into Os[p_loc][m_loc] (stride OSTR=67)
    float* Os = pool;            // 128*67 = 8576 floats
    float ebv[8];
#pragma unroll
    for (int pj = 0; pj < 8; pj++) {
        const int p = pbase + tp8 + pj;
        ebv[pj] = (p < PRED) ? g_eb[p] : 0.f;
    }
#pragma unroll
    for (int mi = 0; mi < 8; mi++) {
        const int mloc = (mi < 4) ? (tm4 + mi) : (tm4 + 32 + (mi - 4));
        const int m = mbase + mloc;
        const float mean = g_mean[m];
        const float sd   = g_std[m];
        const int bi = m / CIN;
        const int ch = m - bi * CIN;
        const float abv = ab[ch];
        const float scale = sd / (aw[ch] + 1e-10f);
#pragma unroll
        for (int pj = 0; pj < 4; pj++) {
            const float2 c = upk2(acc[mi][pj]);
            Os[(tp8 + 2*pj    )*OSTR + mloc] = (c.x + ebv[2*pj    ] - abv) * scale + mean;
            Os[(tp8 + 2*pj + 1)*OSTR + mloc] = (c.y + ebv[2*pj + 1] - abv) * scale + mean;
        }
    }
    __syncthreads();

    // coalesced global store: lanes sweep m (64), two phases sweep p
    const int ml = tid & 63;
    const int ph = tid >> 6;            // 0/1
    const int m  = mbase + ml;
    if (m < M_TOT) {
        const int bi = m / CIN;
        const int ch = m - bi * CIN;
        float* ob = out + (size_t)bi * ROW_STRIDE + ch;
        const int plim = (PRED - pbase < 128) ? (PRED - pbase) : 128;
        for (int pl = ph; pl < plim; pl += 2)
            ob[(size_t)(pbase + pl) * CIN] = Os[pl*OSTR + ml];
    }
}

// ---------------- launcher: 4 graph nodes ----------------
extern "C" void kernel_launch(void* const* d_in, const int* in_sizes, int n_in,
                              void* d_out, int out_size) {
    (void)in_sizes; (void)n_in; (void)out_size;
    const float* x  = (const float*)d_in[0];   // x_enc (16,720,321)
    const float* A  = (const float*)d_in[1];   // A (64,64)
    const float* Bv = (const float*)d_in[2];   // B_vec (64)
    const float* E  = (const float*)d_in[3];   // eval_matrix (720,64)
    const float* W  = (const float*)d_in[4];   // W_mlp (64,64)
    const float* bm = (const float*)d_in[5];   // b_mlp (64)
    const float* aw = (const float*)d_in[6];   // affine_weight (321)
    const float* ab = (const float*)d_in[7];   // affine_bias (321)
    float* out = (float*)d_out;

    const int buildk_smem = (6*NORD*TSTRIDE + 2*NORD*NORD) * (int)sizeof(float); // 137216
    cudaFuncSetAttribute(buildk_kernel, cudaFuncAttributeMaxDynamicSharedMemorySize, buildk_smem);
    cudaFuncSetAttribute(gemm2_kernel, cudaFuncAttributePreferredSharedMemoryCarveout, 100);
    cudaFuncSetAttribute(gemm1_kernel, cudaFuncAttributePreferredSharedMemoryCarveout, 100);

    buildk_kernel<<<NCHAIN + 16, 256, buildk_smem>>>(A, Bv, E, W, bm);
    gemm1_kernel<<<dim3(MPAD/128, TSPLIT), 128>>>(x);
    fuse_kernel<<<MPAD/64, 256>>>(aw, ab);
    gemm2_kernel<<<dim3(MPAD/64, 6), 128>>>(out, aw, ab);
}

// round 14
// speedup vs baseline: 1.1210x; 1.0174x over previous
#include <cuda_runtime.h>

// Problem constants
#define BATCH 16
#define SEQ   720
#define CIN   321
#define NORD  64
#define PRED  720
#define M_TOT (BATCH*CIN)        // 5136
#define MPAD  5376               // 84*64
#define TSPLIT 12
#define TCHUNK 60                // 720/12
#define KCH   20                 // k-chunk in gemm1 (3 per TCHUNK)
#define ROW_STRIDE (SEQ*CIN)     // 231120
#define TSTRIDE 68               // padded transpose stride (floats)
#define NCHAIN 32                // chains in buildk (A^32 stride)
#define OSTR  67                 // epilogue staging stride (2-way max)

typedef unsigned long long ull;

// ---------------- packed f32x2 helpers ----------------
__device__ __forceinline__ ull fma2(ull a, ull b, ull c) {
    ull d;
    asm("fma.rn.f32x2 %0, %1, %2, %3;" : "=l"(d) : "l"(a), "l"(b), "l"(c));
    return d;
}
__device__ __forceinline__ ull dup2(float x) {
    ull d; asm("mov.b64 %0, {%1, %1};" : "=l"(d) : "f"(x)); return d;
}
__device__ __forceinline__ float2 upk2(ull v) {
    float x, y; asm("mov.b64 {%0, %1}, %2;" : "=f"(x), "=f"(y) : "l"(v));
    return make_float2(x, y);
}

// ---------------- device scratch ----------------
__device__ float g_Kt   [PRED*NORD];        // Kt[t][n] = (A^(719-t) B)[n]
__device__ float g_Spart[NCHAIN*NORD];
__device__ float g_EWT  [NORD*PRED];        // (E @ W) transposed: [n][p]
__device__ float g_eb   [PRED];             // E @ b_mlp
__device__ float g_XK   [TSPLIT][MPAD*NORD];
__device__ float g_XKpT [NORD*MPAD];        // alpha-folded GEMM2 operand, [n][m]
__device__ float g_rsum [TSPLIT][MPAD];
__device__ float g_rsq  [TSPLIT][MPAD];
__device__ float g_mean [MPAD];
__device__ float g_std  [MPAD];

// ============================================================================
// buildk: blocks 0..31: A^2..A^32 powers (redundant per block), seed A^r B,
// 23-step chain with A^32. Blocks 32..47: EWT = (E@W)^T and eb = E@b.
// ============================================================================
__global__ void __launch_bounds__(256) buildk_kernel(
    const float* __restrict__ A, const float* __restrict__ Bv,
    const float* __restrict__ E, const float* __restrict__ W,
    const float* __restrict__ bm)
{
    extern __shared__ float sh[];
    const int tid = threadIdx.x;
    const int bid = blockIdx.x;

    if (bid >= NCHAIN) {
        float* Wsh = sh;               // 4096
        float* Esh = sh + 4096;        // 45*64
        __shared__ float bsh[NORD];
        const int e = bid - NCHAIN;
        for (int i = tid; i < NORD*NORD; i += 256) Wsh[i] = W[i];
        for (int i = tid; i < 45*NORD; i += 256)  Esh[i] = E[e*45*NORD + i];
        if (tid < NORD) bsh[tid] = bm[tid];
        __syncthreads();
        for (int idx = tid; idx < 45*NORD; idx += 256) {
            const int pl = idx >> 6, m = idx & 63;
            float a0 = 0.f, a1 = 0.f;
#pragma unroll
            for (int n = 0; n < NORD; n += 2) {
                a0 += Esh[pl*NORD + n    ] * Wsh[(n    )*NORD + m];
                a1 += Esh[pl*NORD + n + 1] * Wsh[(n + 1)*NORD + m];
            }
            g_EWT[(size_t)m*PRED + e*45 + pl] = a0 + a1;
        }
        if (tid < 45) {
            float a = 0.f;
#pragma unroll
            for (int n = 0; n < NORD; n++) a += Esh[tid*NORD + n] * bsh[n];
            g_eb[e*45 + tid] = a;
        }
        return;
    }

    float* TP[6];
#pragma unroll
    for (int i = 0; i < 6; i++) TP[i] = sh + i * NORD * TSTRIDE;
    float* N0 = sh + 6 * NORD * TSTRIDE;
    float* N1 = N0 + NORD*NORD;
    __shared__ float vsh[NORD];
    __shared__ float pb[256];

    for (int i = tid; i < NORD*NORD; i += 256) N0[i] = A[i];
    __syncthreads();
    for (int i = tid; i < NORD*NORD; i += 256)
        TP[0][(i & 63)*TSTRIDE + (i >> 6)] = N0[i];
    __syncthreads();

    float* srcN = N0;
    float* dstN = N1;
    const int ig = tid >> 4;
    const int jg = tid & 15;
#pragma unroll
    for (int s = 0; s < 5; s++) {
        const float* srcT = TP[s];
        ull acc2[4][2];
#pragma unroll
        for (int ii = 0; ii < 4; ii++) { acc2[ii][0] = 0ull; acc2[ii][1] = 0ull; }
#pragma unroll 8
        for (int k = 0; k < NORD; k++) {
            const float4 a = *(const float4*)&srcT[k*TSTRIDE + ig*4];
            const ulonglong2 b = *(const ulonglong2*)&srcN[k*NORD + jg*4];
            float av[4] = {a.x, a.y, a.z, a.w};
#pragma unroll
            for (int ii = 0; ii < 4; ii++) {
                const ull am = dup2(av[ii]);
                acc2[ii][0] = fma2(am, b.x, acc2[ii][0]);
                acc2[ii][1] = fma2(am, b.y, acc2[ii][1]);
            }
        }
#pragma unroll
        for (int ii = 0; ii < 4; ii++) {
            const float2 lo = upk2(acc2[ii][0]);
            const float2 hi = upk2(acc2[ii][1]);
            float4 v; v.x = lo.x; v.y = lo.y; v.z = hi.x; v.w = hi.y;
            *(float4*)&dstN[(ig*4 + ii)*NORD + jg*4] = v;
        }
        __syncthreads();
        for (int i = tid; i < NORD*NORD; i += 256)
            TP[s+1][(i & 63)*TSTRIDE + (i >> 6)] = dstN[i];
        __syncthreads();
        float* tmp = srcN; srcN = dstN; dstN = tmp;
    }

    const int r = bid;
    const int n = tid & 63, q = tid >> 6;

    if (tid < NORD) vsh[tid] = Bv[tid];
    __syncthreads();
#pragma unroll
    for (int b = 0; b < 5; b++) {
        if ((r >> b) & 1) {
            float p = 0.f;
#pragma unroll
            for (int kk = 0; kk < 16; kk++) {
                const int k = q*16 + kk;
                p += TP[b][k*TSTRIDE + n] * vsh[k];
            }
            pb[tid] = p;
            __syncthreads();
            if (tid < NORD) vsh[tid] = pb[tid] + pb[tid+64] + pb[tid+128] + pb[tid+192];
            __syncthreads();
        }
    }

    const float* T32 = TP[5];
    float sacc = 0.f;
    for (int j = 0; j < 23; j++) {
        const int s_exp = 32*j + r;
        if (s_exp < 720 && tid < NORD) {
            const float u = vsh[tid];
            g_Kt[(719 - s_exp)*NORD + tid] = u;
            sacc += u;
        }
        if (j < 22) {
            float p = 0.f;
#pragma unroll
            for (int kk = 0; kk < 16; kk++) {
                const int k = q*16 + kk;
                p += T32[k*TSTRIDE + n] * vsh[k];
            }
            pb[tid] = p;
            __syncthreads();
            if (tid < NORD) vsh[tid] = pb[tid] + pb[tid+64] + pb[tid+128] + pb[tid+192];
            __syncthreads();
        }
    }
    if (tid < NORD) g_Spart[r*NORD + tid] = sacc;
}

// ============================================================================
// GEMM1: XK[m,n] = sum_t x[m,t] * Kt[t,n], fused mean/var partials.
// grid (84, 12), block 64. Mtile=64, N=64. Per thread 8m x 8n (4 m-pairs),
// R8-style pipelined inner loop (4 LDS.128 + 8 dup + 32 FFMA2 per warp-k).
// ============================================================================
__global__ void __launch_bounds__(64, 8) gemm1_kernel(const float* __restrict__ x) {
    __shared__ __align__(16) float Xs[KCH][64];
    __shared__ __align__(16) float Ks[KCH][64];

    const int tid   = threadIdx.x;
    const int mbase = blockIdx.x * 64;
    const int h     = blockIdx.y;
    const int t0    = h * TCHUNK;

    const int m_load = mbase + tid;
    const int bidx   = m_load / CIN;
    const int chl    = m_load - bidx * CIN;
    const float* xrow = x + (size_t)bidx * ROW_STRIDE + chl;
    const bool mval   = (m_load < M_TOT);

    const int tm = tid >> 3;     // 0..7 -> m = mbase + tm*8 + 0..7
    const int tn = tid & 7;      // n = tn*4 + {0..3} and {32..35}
    const int tm8 = tm * 8;
    const int tn4 = tn * 4;

    ull acc[4][8];               // [m-pair][nj]
#pragma unroll
    for (int i = 0; i < 4; i++)
#pragma unroll
        for (int j = 0; j < 8; j++) acc[i][j] = 0ull;
    float psum = 0.f, psq = 0.f;

    for (int kt = 0; kt < TCHUNK/KCH; kt++) {
        const int tb = t0 + kt*KCH;
#pragma unroll
        for (int tt = 0; tt < KCH; tt++) {
            float xv = mval ? xrow[(size_t)(tb + tt) * CIN] : 0.f;
            Xs[tt][tid] = xv;
            psum += xv;
            psq  += xv * xv;
        }
#pragma unroll
        for (int i = 0; i < KCH; i++) {       // 20 loads: KCH*64/64
            const int idx = tid + i*64;
            const int tt = idx >> 6, nn = idx & 63;
            Ks[tt][nn] = g_Kt[(tb + tt) * NORD + nn];
        }
        __syncthreads();

        // software-pipelined inner loop
        ulonglong2 A0 = *(const ulonglong2*)&Xs[0][tm8];
        ulonglong2 A1 = *(const ulonglong2*)&Xs[0][tm8 + 4];
        float4 B0 = *(const float4*)&Ks[0][tn4];
        float4 B1 = *(const float4*)&Ks[0][tn4 + 32];
#pragma unroll 5
        for (int tt = 0; tt < KCH; tt++) {
            const int tnx = (tt + 1 < KCH) ? tt + 1 : 0;
            const ulonglong2 nA0 = *(const ulonglong2*)&Xs[tnx][tm8];
            const ulonglong2 nA1 = *(const ulonglong2*)&Xs[tnx][tm8 + 4];
            const float4 nB0 = *(const float4*)&Ks[tnx][tn4];
            const float4 nB1 = *(const float4*)&Ks[tnx][tn4 + 32];
            const ull ap[4] = {A0.x, A0.y, A1.x, A1.y};
            const ull bd[8] = {dup2(B0.x), dup2(B0.y), dup2(B0.z), dup2(B0.w),
                               dup2(B1.x), dup2(B1.y), dup2(B1.z), dup2(B1.w)};
#pragma unroll
            for (int mp = 0; mp < 4; mp++)
#pragma unroll
                for (int nj = 0; nj < 8; nj++)
                    acc[mp][nj] = fma2(ap[mp], bd[nj], acc[mp][nj]);
            A0 = nA0; A1 = nA1; B0 = nB0; B1 = nB1;
        }
        __syncthreads();
    }

    float* xk = g_XK[h];
#pragma unroll
    for (int mp = 0; mp < 4; mp++) {
        const int m0 = mbase + tm8 + mp*2;
        float2 c[8];
#pragma unroll
        for (int nj = 0; nj < 8; nj++) c[nj] = upk2(acc[mp][nj]);
        float4 lo0; lo0.x = c[0].x; lo0.y = c[1].x; lo0.z = c[2].x; lo0.w = c[3].x;
        float4 lo1; lo1.x = c[4].x; lo1.y = c[5].x; lo1.z = c[6].x; lo1.w = c[7].x;
        float4 hi0; hi0.x = c[0].y; hi0.y = c[1].y; hi0.z = c[2].y; hi0.w = c[3].y;
        float4 hi1; hi1.x = c[4].y; hi1.y = c[5].y; hi1.z = c[6].y; hi1.w = c[7].y;
        *(float4*)&xk[(size_t)m0 * NORD + tn4]          = lo0;
        *(float4*)&xk[(size_t)m0 * NORD + tn4 + 32]     = lo1;
        *(float4*)&xk[(size_t)(m0+1) * NORD + tn4]      = hi0;
        *(float4*)&xk[(size_t)(m0+1) * NORD + tn4 + 32] = hi1;
    }
    // each thread owns one m column entirely: direct partial-stat store
    g_rsum[h][m_load] = psum;
    g_rsq [h][m_load] = psq;
}

// ============================================================================
// fuse: reduce t-split partials + stats + S + alpha/beta fold + transpose.
// XKpT[n, m] = alpha_m * sum_h XK[h][m,n] + beta_m * S[n]
// grid MPAD/64, block 256.
// ============================================================================
__global__ void __launch_bounds__(256) fuse_kernel(const float* __restrict__ aw,
                                                   const float* __restrict__ ab) {
    __shared__ float TT[64*65];
    __shared__ float alpha_s[64], beta_s[64], Ssh[64];
    const int tid = threadIdx.x;
    const int mb  = blockIdx.x * 64;

    if (tid < 64) {
        const int m = mb + tid;
        float s = 0.f, qq = 0.f;
#pragma unroll
        for (int h = 0; h < TSPLIT; h++) { s += g_rsum[h][m]; qq += g_rsq[h][m]; }
        const float mean = s * (1.0f / 720.0f);
        const float var  = qq * (1.0f / 720.0f) - mean * mean;
        const float sd   = sqrtf(var + 1e-5f);
        const int bidx = m / CIN;
        const int ch   = m - bidx * CIN;
        const float al = aw[ch] / sd;
        alpha_s[tid] = al;
        beta_s[tid]  = ab[ch] - mean * al;
        g_mean[m] = mean;
        g_std[m]  = sd;
    } else if (tid < 128) {
        const int nn = tid - 64;
        float s = 0.f;
#pragma unroll
        for (int rr = 0; rr < NCHAIN; rr++) s += g_Spart[rr*NORD + nn];
        Ssh[nn] = s;
    }
    __syncthreads();

#pragma unroll
    for (int i = 0; i < 16; i++) {
        const int idx = i*256 + tid;           // 0..4095
        const int ml = idx >> 6, nn = idx & 63;
        float v = 0.f;
#pragma unroll
        for (int h = 0; h < TSPLIT; h++) v += g_XK[h][(size_t)(mb + ml)*NORD + nn];
        TT[nn*65 + ml] = alpha_s[ml]*v + beta_s[ml]*Ssh[nn];
    }
    __syncthreads();
#pragma unroll
    for (int i = 0; i < 16; i++) {
        const int idx = i*256 + tid;
        const int nn = idx >> 6, ml = idx & 63;
        g_XKpT[(size_t)nn*MPAD + mb + ml] = TT[nn*65 + ml];
    }
}

// ============================================================================
// GEMM2 + epilogue: pre[m,p] = sum_n XKpT[n,m] EWT[n,p] + eb[p];
// out = (pre - ab)/(aw+1e-10)*sd + mean. Coalesced stores via smem staging.
// grid (84, 12), block 64. Mtile=64, Ptile=64, K=64 resident.
// Per thread 8m x 8p (4 m-pairs), R8-style pipelined inner loop.
// ============================================================================
__global__ void __launch_bounds__(64, 8) gemm2_kernel(float* __restrict__ out,
                                                      const float* __restrict__ aw,
                                                      const float* __restrict__ ab) {
    __shared__ __align__(16) float pool[8192];    // 32 KB
    float* Xs = pool;           // [64 k][64 m]
    float* Es = pool + 4096;    // [64 k][64 p]

    const int tid   = threadIdx.x;
    const int mbase = blockIdx.x * 64;
    const int pbase = blockIdx.y * 64;
    const int tm = tid & 7;      // m = mbase + tm*4 + {0..3, 32..35}
    const int tp = tid >> 3;     // p = pbase + tp*8 + 0..7  (tp 0..7)
    const int tm4 = tm * 4;
    const int tp8 = tp * 8;

    // stage Xs: 16 float4 per thread, coalesced conflict-free
#pragma unroll
    for (int i = 0; i < 16; i++) {
        const int idx = tid + i*64;             // 0..1023
        const int n = idx >> 4, mg = idx & 15;
        *(float4*)&Xs[n*64 + mg*4] =
            *(const float4*)&g_XKpT[(size_t)n*MPAD + mbase + mg*4];
    }
    // stage Es with p guard: 16 float4 per thread
#pragma unroll
    for (int i = 0; i < 16; i++) {
        const int idx = tid + i*64;             // 0..1023
        const int n = idx >> 4, pg = idx & 15;
        const int p = pbase + pg*4;
        float4 v = make_float4(0.f, 0.f, 0.f, 0.f);
        if (p < PRED) v = *(const float4*)&g_EWT[(size_t)n*PRED + p];
        *(float4*)&Es[n*64 + pg*4] = v;
    }
    __syncthreads();

    ull acc[4][8];               // [m-pair][pj]
#pragma unroll
    for (int i = 0; i < 4; i++)
#pragma unroll
        for (int j = 0; j < 8; j++) acc[i][j] = 0ull;

    // software-pipelined K loop
    ulonglong2 A0 = *(const ulonglong2*)&Xs[tm4];
    ulonglong2 A1 = *(const ulonglong2*)&Xs[tm4 + 32];
    float4 B0 = *(const float4*)&Es[tp8];
    float4 B1 = *(const float4*)&Es[tp8 + 4];
#pragma unroll 8
    for (int k = 0; k < 64; k++) {
        const int kn = (k + 1) & 63;
        const ulonglong2 nA0 = *(const ulonglong2*)&Xs[kn*64 + tm4];
        const ulonglong2 nA1 = *(const ulonglong2*)&Xs[kn*64 + tm4 + 32];
        const float4 nB0 = *(const float4*)&Es[kn*64 + tp8];
        const float4 nB1 = *(const float4*)&Es[kn*64 + tp8 + 4];
        const ull ap[4] = {A0.x, A0.y, A1.x, A1.y};
        const ull bd[8] = {dup2(B0.x), dup2(B0.y), dup2(B0.z), dup2(B0.w),
                           dup2(B1.x), dup2(B1.y), dup2(B1.z), dup2(B1.w)};
#pragma unroll
        for (int mp = 0; mp < 4; mp++)
#pragma unroll
            for (int pj = 0; pj < 8; pj++)
                acc[mp][pj] = fma2(ap[mp], bd[pj], acc[mp][pj]);
        A0 = nA0; A1 = nA1; B0 = nB0; B1 = nB1;
    }
    __syncthreads();   // done reading Xs/Es; pool reused as Os

    // epilogue staged into Os[p_loc][m_loc] (stride OSTR=67): 64p x 67 = 17KB
    float* Os = pool;
    float ebv[8];
#pragma unroll
    for (int pj = 0; pj < 8; pj++) {
        const int p = pbase + tp8 + pj;
        ebv[pj] = (p < PRED) ? g_eb[p] : 0.f;
    }
#pragma unroll
    for (int mp = 0; mp < 4; mp++) {
        const int mloc0 = (mp < 2) ? (tm4 + 2*mp) : (tm4 + 32 + 2*(mp - 2));
        float2 c[8];
#pragma unroll
        for (int pj = 0; pj < 8; pj++) c[pj] = upk2(acc[mp][pj]);
#pragma unroll
        for (int w = 0; w < 2; w++) {
            const int m = mbase + mloc0 + w;
            const float mean = g_mean[m];
            const float sd   = g_std[m];
            const int bi = m / CIN;
            const int ch = m - bi * CIN;
            const float abv = ab[ch];
            const float scale = sd / (aw[ch] + 1e-10f);
#pragma unroll
            for (int pj = 0; pj < 8; pj++) {
                const float val = w ? c[pj].y : c[pj].x;
                Os[(tp8 + pj)*OSTR + mloc0 + w] = (val + ebv[pj] - abv) * scale + mean;
            }
        }
    }
    __syncthreads();

    // coalesced global store: 64 lanes sweep m, loop sweeps p
    const int m = mbase + tid;
    if (m < M_TOT) {
        const int bi = m / CIN;
        const int ch = m - bi * CIN;
        float* ob = out + (size_t)bi * ROW_STRIDE + ch;
        const int plim = (PRED - pbase < 64) ? (PRED - pbase) : 64;
        for (int pl = 0; pl < plim; pl++)
            ob[(size_t)(pbase + pl) * CIN] = Os[pl*OSTR + tid];
    }
}

// ---------------- launcher: 4 graph nodes ----------------
extern "C" void kernel_launch(void* const* d_in, const int* in_sizes, int n_in,
                              void* d_out, int out_size) {
    (void)in_sizes; (void)n_in; (void)out_size;
    const float* x  = (const float*)d_in[0];   // x_enc (16,720,321)
    const float* A  = (const float*)d_in[1];   // A (64,64)
    const float* Bv = (const float*)d_in[2];   // B_vec (64)
    const float* E  = (const float*)d_in[3];   // eval_matrix (720,64)
    const float* W  = (const float*)d_in[4];   // W_mlp (64,64)
    const float* bm = (const float*)d_in[5];   // b_mlp (64)
    const float* aw = (const float*)d_in[6];   // affine_weight (321)
    const float* ab = (const float*)d_in[7];   // affine_bias (321)
    float* out = (float*)d_out;

    const int buildk_smem = (6*NORD*TSTRIDE + 2*NORD*NORD) * (int)sizeof(float); // 137216
    cudaFuncSetAttribute(buildk_kernel, cudaFuncAttributeMaxDynamicSharedMemorySize, buildk_smem);
    cudaFuncSetAttribute(gemm2_kernel, cudaFuncAttributePreferredSharedMemoryCarveout, 100);
    cudaFuncSetAttribute(gemm1_kernel, cudaFuncAttributePreferredSharedMemoryCarveout, 100);

    buildk_kernel<<<NCHAIN + 16, 256, buildk_smem>>>(A, Bv, E, W, bm);
    gemm1_kernel<<<dim3(MPAD/64, TSPLIT), 64>>>(x);
    fuse_kernel<<<MPAD/64, 256>>>(aw, ab);
    gemm2_kernel<<<dim3(MPAD/64, 12), 64>>>(out, aw, ab);
}

// round 15
// speedup vs baseline: 1.2122x; 1.0813x over previous
#include <cuda_runtime.h>
#include <cstdint>

// Problem constants
#define BATCH 16
#define SEQ   720
#define CIN   321
#define NORD  64
#define PRED  720
#define M_TOT (BATCH*CIN)        // 5136
#define MPAD  5376               // 84*64
#define TSPLIT 15
#define TCHUNK 48                // 720/15
#define ROW_STRIDE (SEQ*CIN)     // 231120
#define TSTRIDE 68               // buildk transpose stride
#define NCHAIN 32
#define XSTR  72                 // tf32 smem stride (conflict-free for mma lanes)
#define OSTR  67

typedef unsigned long long ull;

// ---------------- helpers ----------------
__device__ __forceinline__ ull fma2(ull a, ull b, ull c) {
    ull d;
    asm("fma.rn.f32x2 %0, %1, %2, %3;" : "=l"(d) : "l"(a), "l"(b), "l"(c));
    return d;
}
__device__ __forceinline__ ull dup2(float x) {
    ull d; asm("mov.b64 %0, {%1, %1};" : "=l"(d) : "f"(x)); return d;
}
__device__ __forceinline__ float2 upk2(ull v) {
    float x, y; asm("mov.b64 {%0, %1}, %2;" : "=f"(x), "=f"(y) : "l"(v));
    return make_float2(x, y);
}
__device__ __forceinline__ float to_tf32(float x) {
    uint32_t r; asm("cvt.rna.tf32.f32 %0, %1;" : "=r"(r) : "f"(x));
    return __uint_as_float(r);
}
__device__ __forceinline__ void mma_tf32(float c[4],
    uint32_t a0, uint32_t a1, uint32_t a2, uint32_t a3,
    uint32_t b0, uint32_t b1) {
    asm volatile(
        "mma.sync.aligned.m16n8k8.row.col.f32.tf32.tf32.f32 "
        "{%0,%1,%2,%3}, {%4,%5,%6,%7}, {%8,%9}, {%0,%1,%2,%3};"
        : "+f"(c[0]), "+f"(c[1]), "+f"(c[2]), "+f"(c[3])
        : "r"(a0), "r"(a1), "r"(a2), "r"(a3), "r"(b0), "r"(b1));
}
#define U(v) __float_as_uint(v)

// ---------------- device scratch ----------------
__device__ float g_Kt   [PRED*NORD];
__device__ float g_Spart[NCHAIN*NORD];
__device__ float g_EWT  [NORD*PRED];        // (E@W)^T : [n][p]
__device__ float g_eb   [PRED];
__device__ float g_XK   [TSPLIT][MPAD*NORD];
__device__ float g_XKpT [NORD*MPAD];        // alpha-folded: [n][m]
__device__ float g_rsum [TSPLIT][MPAD];
__device__ float g_rsq  [TSPLIT][MPAD];
__device__ float g_mean [MPAD];
__device__ float g_std  [MPAD];

// ============================================================================
// buildk (unchanged from R8 baseline)
// ============================================================================
__global__ void __launch_bounds__(256) buildk_kernel(
    const float* __restrict__ A, const float* __restrict__ Bv,
    const float* __restrict__ E, const float* __restrict__ W,
    const float* __restrict__ bm)
{
    extern __shared__ float sh[];
    const int tid = threadIdx.x;
    const int bid = blockIdx.x;

    if (bid >= NCHAIN) {
        float* Wsh = sh;
        float* Esh = sh + 4096;
        __shared__ float bsh[NORD];
        const int e = bid - NCHAIN;
        for (int i = tid; i < NORD*NORD; i += 256) Wsh[i] = W[i];
        for (int i = tid; i < 45*NORD; i += 256)  Esh[i] = E[e*45*NORD + i];
        if (tid < NORD) bsh[tid] = bm[tid];
        __syncthreads();
        for (int idx = tid; idx < 45*NORD; idx += 256) {
            const int pl = idx >> 6, m = idx & 63;
            float a0 = 0.f, a1 = 0.f;
#pragma unroll
            for (int n = 0; n < NORD; n += 2) {
                a0 += Esh[pl*NORD + n    ] * Wsh[(n    )*NORD + m];
                a1 += Esh[pl*NORD + n + 1] * Wsh[(n + 1)*NORD + m];
            }
            g_EWT[(size_t)m*PRED + e*45 + pl] = a0 + a1;
        }
        if (tid < 45) {
            float a = 0.f;
#pragma unroll
            for (int n = 0; n < NORD; n++) a += Esh[tid*NORD + n] * bsh[n];
            g_eb[e*45 + tid] = a;
        }
        return;
    }

    float* TP[6];
#pragma unroll
    for (int i = 0; i < 6; i++) TP[i] = sh + i * NORD * TSTRIDE;
    float* N0 = sh + 6 * NORD * TSTRIDE;
    float* N1 = N0 + NORD*NORD;
    __shared__ float vsh[NORD];
    __shared__ float pb[256];

    for (int i = tid; i < NORD*NORD; i += 256) N0[i] = A[i];
    __syncthreads();
    for (int i = tid; i < NORD*NORD; i += 256)
        TP[0][(i & 63)*TSTRIDE + (i >> 6)] = N0[i];
    __syncthreads();

    float* srcN = N0;
    float* dstN = N1;
    const int ig = tid >> 4;
    const int jg = tid & 15;
#pragma unroll
    for (int s = 0; s < 5; s++) {
        const float* srcT = TP[s];
        ull acc2[4][2];
#pragma unroll
        for (int ii = 0; ii < 4; ii++) { acc2[ii][0] = 0ull; acc2[ii][1] = 0ull; }
#pragma unroll 8
        for (int k = 0; k < NORD; k++) {
            const float4 a = *(const float4*)&srcT[k*TSTRIDE + ig*4];
            const ulonglong2 b = *(const ulonglong2*)&srcN[k*NORD + jg*4];
            float av[4] = {a.x, a.y, a.z, a.w};
#pragma unroll
            for (int ii = 0; ii < 4; ii++) {
                const ull am = dup2(av[ii]);
                acc2[ii][0] = fma2(am, b.x, acc2[ii][0]);
                acc2[ii][1] = fma2(am, b.y, acc2[ii][1]);
            }
        }
#pragma unroll
        for (int ii = 0; ii < 4; ii++) {
            const float2 lo = upk2(acc2[ii][0]);
            const float2 hi = upk2(acc2[ii][1]);
            float4 v; v.x = lo.x; v.y = lo.y; v.z = hi.x; v.w = hi.y;
            *(float4*)&dstN[(ig*4 + ii)*NORD + jg*4] = v;
        }
        __syncthreads();
        for (int i = tid; i < NORD*NORD; i += 256)
            TP[s+1][(i & 63)*TSTRIDE + (i >> 6)] = dstN[i];
        __syncthreads();
        float* tmp = srcN; srcN = dstN; dstN = tmp;
    }

    const int r = bid;
    const int n = tid & 63, q = tid >> 6;

    if (tid < NORD) vsh[tid] = Bv[tid];
    __syncthreads();
#pragma unroll
    for (int b = 0; b < 5; b++) {
        if ((r >> b) & 1) {
            float p = 0.f;
#pragma unroll
            for (int kk = 0; kk < 16; kk++) {
                const int k = q*16 + kk;
                p += TP[b][k*TSTRIDE + n] * vsh[k];
            }
            pb[tid] = p;
            __syncthreads();
            if (tid < NORD) vsh[tid] = pb[tid] + pb[tid+64] + pb[tid+128] + pb[tid+192];
            __syncthreads();
        }
    }

    const float* T32 = TP[5];
    float sacc = 0.f;
    for (int j = 0; j < 23; j++) {
        const int s_exp = 32*j + r;
        if (s_exp < 720 && tid < NORD) {
            const float u = vsh[tid];
            g_Kt[(719 - s_exp)*NORD + tid] = u;
            sacc += u;
        }
        if (j < 22) {
            float p = 0.f;
#pragma unroll
            for (int kk = 0; kk < 16; kk++) {
                const int k = q*16 + kk;
                p += T32[k*TSTRIDE + n] * vsh[k];
            }
            pb[tid] = p;
            __syncthreads();
            if (tid < NORD) vsh[tid] = pb[tid] + pb[tid+64] + pb[tid+128] + pb[tid+192];
            __syncthreads();
        }
    }
    if (tid < NORD) g_Spart[r*NORD + tid] = sacc;
}

// ============================================================================
// GEMM1 (tensor): XK[m,n] = sum_t x[m,t]*Kt[t,n] via tf32 m16n8k8 mma.
// grid (84, 15), block 128 (4 warps). Mtile=64 (16 m-rows/warp), N=64,
// K-chunk = 48 (single smem stage, 6 k-steps of 8). Fused mean/var partials.
// ============================================================================
__global__ void __launch_bounds__(128) gemm1_kernel(const float* __restrict__ x) {
    __shared__ __align__(16) float Xs[TCHUNK*XSTR];   // [t][m] tf32
    __shared__ __align__(16) float Ks[TCHUNK*XSTR];   // [t][n] tf32
    __shared__ float sred[128], sqred[128];

    const int tid   = threadIdx.x;
    const int mbase = blockIdx.x * 64;
    const int h     = blockIdx.y;
    const int t0    = h * TCHUNK;

    const int ml   = tid & 63;
    const int trow = tid >> 6;           // 0/1
    const int m_load = mbase + ml;
    const int bidx   = m_load / CIN;
    const int chl    = m_load - bidx * CIN;
    const float* xrow = x + (size_t)bidx * ROW_STRIDE + chl;
    const bool mval   = (m_load < M_TOT);

    float psum = 0.f, psq = 0.f;
#pragma unroll 8
    for (int i = 0; i < TCHUNK/2; i++) {
        const int t = trow + 2*i;
        float xv = mval ? xrow[(size_t)(t0 + t) * CIN] : 0.f;
        psum += xv;
        psq  += xv * xv;
        Xs[t*XSTR + ml] = to_tf32(xv);
    }
#pragma unroll 8
    for (int i = 0; i < (TCHUNK*64)/128; i++) {
        const int idx = tid + i*128;
        const int t = idx >> 6, n = idx & 63;
        Ks[t*XSTR + n] = to_tf32(g_Kt[(t0 + t)*NORD + n]);
    }
    __syncthreads();

    const int wid  = tid >> 5;
    const int lane = tid & 31;
    const int gid  = lane >> 2;
    const int tid4 = lane & 3;
    const int w16  = wid * 16;

    float c[8][4];
#pragma unroll
    for (int i = 0; i < 8; i++)
#pragma unroll
        for (int j = 0; j < 4; j++) c[i][j] = 0.f;

#pragma unroll
    for (int ks = 0; ks < TCHUNK/8; ks++) {
        const int kb = ks * 8;
        const int ar = (kb + tid4)*XSTR + w16 + gid;
        const uint32_t a0 = U(Xs[ar]);
        const uint32_t a1 = U(Xs[ar + 8]);
        const uint32_t a2 = U(Xs[ar + 4*XSTR]);
        const uint32_t a3 = U(Xs[ar + 4*XSTR + 8]);
#pragma unroll
        for (int ns = 0; ns < 8; ns++) {
            const int br = (kb + tid4)*XSTR + ns*8 + gid;
            const uint32_t b0 = U(Ks[br]);
            const uint32_t b1 = U(Ks[br + 4*XSTR]);
            mma_tf32(c[ns], a0, a1, a2, a3, b0, b1);
        }
    }

    float* xk = g_XK[h];
    const int row0 = mbase + w16 + gid;
#pragma unroll
    for (int ns = 0; ns < 8; ns++) {
        const int nc = ns*8 + 2*tid4;
        float2 v01; v01.x = c[ns][0]; v01.y = c[ns][1];
        float2 v23; v23.x = c[ns][2]; v23.y = c[ns][3];
        *(float2*)&xk[(size_t)row0 * NORD + nc]       = v01;
        *(float2*)&xk[(size_t)(row0+8) * NORD + nc]   = v23;
    }
    sred[tid]  = psum;
    sqred[tid] = psq;
    __syncthreads();
    if (tid < 64) {
        g_rsum[h][mbase + tid] = sred[tid] + sred[tid + 64];
        g_rsq [h][mbase + tid] = sqred[tid] + sqred[tid + 64];
    }
}

// ============================================================================
// fuse: reduce t-split partials + stats + S + alpha/beta fold + transpose.
// ============================================================================
__global__ void __launch_bounds__(256) fuse_kernel(const float* __restrict__ aw,
                                                   const float* __restrict__ ab) {
    __shared__ float TT[64*65];
    __shared__ float alpha_s[64], beta_s[64], Ssh[64];
    const int tid = threadIdx.x;
    const int mb  = blockIdx.x * 64;

    if (tid < 64) {
        const int m = mb + tid;
        float s = 0.f, qq = 0.f;
#pragma unroll
        for (int h = 0; h < TSPLIT; h++) { s += g_rsum[h][m]; qq += g_rsq[h][m]; }
        const float mean = s * (1.0f / 720.0f);
        const float var  = qq * (1.0f / 720.0f) - mean * mean;
        const float sd   = sqrtf(var + 1e-5f);
        const int bidx = m / CIN;
        const int ch   = m - bidx * CIN;
        const float al = aw[ch] / sd;
        alpha_s[tid] = al;
        beta_s[tid]  = ab[ch] - mean * al;
        g_mean[m] = mean;
        g_std[m]  = sd;
    } else if (tid < 128) {
        const int nn = tid - 64;
        float s = 0.f;
#pragma unroll
        for (int rr = 0; rr < NCHAIN; rr++) s += g_Spart[rr*NORD + nn];
        Ssh[nn] = s;
    }
    __syncthreads();

#pragma unroll
    for (int i = 0; i < 16; i++) {
        const int idx = i*256 + tid;
        const int mlx = idx >> 6, nn = idx & 63;
        float v = 0.f;
#pragma unroll
        for (int h = 0; h < TSPLIT; h++) v += g_XK[h][(size_t)(mb + mlx)*NORD + nn];
        TT[nn*65 + mlx] = alpha_s[mlx]*v + beta_s[mlx]*Ssh[nn];
    }
    __syncthreads();
#pragma unroll
    for (int i = 0; i < 16; i++) {
        const int idx = i*256 + tid;
        const int nn = idx >> 6, mlx = idx & 63;
        g_XKpT[(size_t)nn*MPAD + mb + mlx] = TT[nn*65 + mlx];
    }
}

// ============================================================================
// GEMM2 (tensor) + epilogue: pre[m,p] = sum_n XKpT[n,m]*EWT[n,p] + eb[p];
// out = (pre - ab)/(aw+1e-10)*sd + mean. tf32 m16n8k8 mma, K=64 resident.
// grid (84, 12), block 128 (4 warps). Mtile=64, Ptile=64.
// ============================================================================
__global__ void __launch_bounds__(128) gemm2_kernel(float* __restrict__ out,
                                                    const float* __restrict__ aw,
                                                    const float* __restrict__ ab) {
    __shared__ __align__(16) float pool[9216];    // 36.9 KB
    float* Xs2 = pool;              // [n][m] tf32, stride 72
    float* Es  = pool + 64*XSTR;    // [n][p] tf32, stride 72

    const int tid   = threadIdx.x;
    const int mbase = blockIdx.x * 64;
    const int pbase = blockIdx.y * 64;

    // stage (with tf32 cvt)
#pragma unroll 8
    for (int i = 0; i < 32; i++) {
        const int idx = tid + i*128;
        const int n = idx >> 6, mg = idx & 63;
        Xs2[n*XSTR + mg] = to_tf32(g_XKpT[(size_t)n*MPAD + mbase + mg]);
    }
#pragma unroll 8
    for (int i = 0; i < 32; i++) {
        const int idx = tid + i*128;
        const int n = idx >> 6, pg = idx & 63;
        const int p = pbase + pg;
        Es[n*XSTR + pg] = (p < PRED) ? to_tf32(g_EWT[(size_t)n*PRED + p]) : 0.f;
    }
    __syncthreads();

    const int wid  = tid >> 5;
    const int lane = tid & 31;
    const int gid  = lane >> 2;
    const int tid4 = lane & 3;
    const int w16  = wid * 16;

    float c[8][4];
#pragma unroll
    for (int i = 0; i < 8; i++)
#pragma unroll
        for (int j = 0; j < 4; j++) c[i][j] = 0.f;

#pragma unroll
    for (int ks = 0; ks < 8; ks++) {
        const int kb = ks * 8;
        const int ar = (kb + tid4)*XSTR + w16 + gid;
        const uint32_t a0 = U(Xs2[ar]);
        const uint32_t a1 = U(Xs2[ar + 8]);
        const uint32_t a2 = U(Xs2[ar + 4*XSTR]);
        const uint32_t a3 = U(Xs2[ar + 4*XSTR + 8]);
#pragma unroll
        for (int ps = 0; ps < 8; ps++) {
            const int br = (kb + tid4)*XSTR + ps*8 + gid;
            const uint32_t b0 = U(Es[br]);
            const uint32_t b1 = U(Es[br + 4*XSTR]);
            mma_tf32(c[ps], a0, a1, a2, a3, b0, b1);
        }
    }
    __syncthreads();   // pool reused as Os

    // epilogue: stage into Os[p_loc][m_loc] (stride 67)
    float* Os = pool;               // 64*67 = 4288 floats
    const int m0 = mbase + w16 + gid;
    const int m1 = m0 + 8;
    const float mean0 = g_mean[m0], sd0 = g_std[m0];
    const float mean1 = g_mean[m1], sd1 = g_std[m1];
    const int bi0 = m0 / CIN, ch0 = m0 - bi0*CIN;
    const int bi1 = m1 / CIN, ch1 = m1 - bi1*CIN;
    const float ab0 = ab[ch0], sc0 = sd0 / (aw[ch0] + 1e-10f);
    const float ab1 = ab[ch1], sc1 = sd1 / (aw[ch1] + 1e-10f);
    const int mloc0 = w16 + gid;

#pragma unroll
    for (int ps = 0; ps < 8; ps++) {
        const int pl0 = ps*8 + 2*tid4;
        const int p0  = pbase + pl0;
        const float e0 = (p0     < PRED) ? g_eb[p0]     : 0.f;
        const float e1 = (p0 + 1 < PRED) ? g_eb[p0 + 1] : 0.f;
        Os[(pl0    )*OSTR + mloc0    ] = (c[ps][0] + e0 - ab0) * sc0 + mean0;
        Os[(pl0 + 1)*OSTR + mloc0    ] = (c[ps][1] + e1 - ab0) * sc0 + mean0;
        Os[(pl0    )*OSTR + mloc0 + 8] = (c[ps][2] + e0 - ab1) * sc1 + mean1;
        Os[(pl0 + 1)*OSTR + mloc0 + 8] = (c[ps][3] + e1 - ab1) * sc1 + mean1;
    }
    __syncthreads();

    // coalesced global store: 64 lanes sweep m, two phases sweep p
    const int mls = tid & 63;
    const int ph  = tid >> 6;            // 0/1
    const int m   = mbase + mls;
    if (m < M_TOT) {
        const int bi = m / CIN;
        const int ch = m - bi * CIN;
        float* ob = out + (size_t)bi * ROW_STRIDE + ch;
        const int plim = (PRED - pbase < 64) ? (PRED - pbase) : 64;
        for (int pl = ph; pl < plim; pl += 2)
            ob[(size_t)(pbase + pl) * CIN] = Os[pl*OSTR + mls];
    }
}

// ---------------- launcher: 4 graph nodes ----------------
extern "C" void kernel_launch(void* const* d_in, const int* in_sizes, int n_in,
                              void* d_out, int out_size) {
    (void)in_sizes; (void)n_in; (void)out_size;
    const float* x  = (const float*)d_in[0];   // x_enc (16,720,321)
    const float* A  = (const float*)d_in[1];   // A (64,64)
    const float* Bv = (const float*)d_in[2];   // B_vec (64)
    const float* E  = (const float*)d_in[3];   // eval_matrix (720,64)
    const float* W  = (const float*)d_in[4];   // W_mlp (64,64)
    const float* bm = (const float*)d_in[5];   // b_mlp (64)
    const float* aw = (const float*)d_in[6];   // affine_weight (321)
    const float* ab = (const float*)d_in[7];   // affine_bias (321)
    float* out = (float*)d_out;

    const int buildk_smem = (6*NORD*TSTRIDE + 2*NORD*NORD) * (int)sizeof(float); // 137216
    cudaFuncSetAttribute(buildk_kernel, cudaFuncAttributeMaxDynamicSharedMemorySize, buildk_smem);

    buildk_kernel<<<NCHAIN + 16, 256, buildk_smem>>>(A, Bv, E, W, bm);
    gemm1_kernel<<<dim3(MPAD/64, TSPLIT), 128>>>(x);
    fuse_kernel<<<MPAD/64, 256>>>(aw, ab);
    gemm2_kernel<<<dim3(MPAD/64, 12), 128>>>(out, aw, ab);
}

// round 16
// speedup vs baseline: 1.2863x; 1.0611x over previous
#include <cuda_runtime.h>
#include <cstdint>

// Problem constants
#define BATCH 16
#define SEQ   720
#define CIN   321
#define NORD  64
#define PRED  720
#define M_TOT (BATCH*CIN)        // 5136
#define MPAD  5376               // 84*64
#define TSPLIT 15
#define TCHUNK 48                // 720/15
#define ROW_STRIDE (SEQ*CIN)     // 231120
#define TSTRIDE 68               // buildk transpose stride
#define NCHAIN 32
#define XSTR  72                 // [k][64] tf32 smem stride (conflict-free)
#define ESTR  136                // [k][128] tf32 smem stride (conflict-free: 136%32=8)
#define OSTR  67

typedef unsigned long long ull;

// ---------------- helpers ----------------
__device__ __forceinline__ ull fma2(ull a, ull b, ull c) {
    ull d;
    asm("fma.rn.f32x2 %0, %1, %2, %3;" : "=l"(d) : "l"(a), "l"(b), "l"(c));
    return d;
}
__device__ __forceinline__ ull dup2(float x) {
    ull d; asm("mov.b64 %0, {%1, %1};" : "=l"(d) : "f"(x)); return d;
}
__device__ __forceinline__ float2 upk2(ull v) {
    float x, y; asm("mov.b64 {%0, %1}, %2;" : "=f"(x), "=f"(y) : "l"(v));
    return make_float2(x, y);
}
__device__ __forceinline__ float to_tf32(float x) {
    uint32_t r; asm("cvt.rna.tf32.f32 %0, %1;" : "=r"(r) : "f"(x));
    return __uint_as_float(r);
}
__device__ __forceinline__ void mma_tf32(float c[4],
    uint32_t a0, uint32_t a1, uint32_t a2, uint32_t a3,
    uint32_t b0, uint32_t b1) {
    asm volatile(
        "mma.sync.aligned.m16n8k8.row.col.f32.tf32.tf32.f32 "
        "{%0,%1,%2,%3}, {%4,%5,%6,%7}, {%8,%9}, {%0,%1,%2,%3};"
        : "+f"(c[0]), "+f"(c[1]), "+f"(c[2]), "+f"(c[3])
        : "r"(a0), "r"(a1), "r"(a2), "r"(a3), "r"(b0), "r"(b1));
}
#define U(v) __float_as_uint(v)

// ---------------- device scratch ----------------
__device__ float g_Kt   [PRED*NORD];        // pre-tf32
__device__ float g_Spart[NCHAIN*NORD];
__device__ float g_EWT  [NORD*PRED];        // (E@W)^T pre-tf32 : [n][p]
__device__ float g_eb   [PRED];
__device__ float g_XK   [TSPLIT][MPAD*NORD];
__device__ float g_XKpT [NORD*MPAD];        // alpha-folded pre-tf32: [n][m]
__device__ float g_rsum [TSPLIT][MPAD];
__device__ float g_rsq  [TSPLIT][MPAD];
__device__ float g_mean [MPAD];
__device__ float g_std  [MPAD];

// ============================================================================
// buildk (R8 structure; Kt/EWT stored tf32-rounded)
// ============================================================================
__global__ void __launch_bounds__(256) buildk_kernel(
    const float* __restrict__ A, const float* __restrict__ Bv,
    const float* __restrict__ E, const float* __restrict__ W,
    const float* __restrict__ bm)
{
    extern __shared__ float sh[];
    const int tid = threadIdx.x;
    const int bid = blockIdx.x;

    if (bid >= NCHAIN) {
        float* Wsh = sh;
        float* Esh = sh + 4096;
        __shared__ float bsh[NORD];
        const int e = bid - NCHAIN;
        for (int i = tid; i < NORD*NORD; i += 256) Wsh[i] = W[i];
        for (int i = tid; i < 45*NORD; i += 256)  Esh[i] = E[e*45*NORD + i];
        if (tid < NORD) bsh[tid] = bm[tid];
        __syncthreads();
        for (int idx = tid; idx < 45*NORD; idx += 256) {
            const int pl = idx >> 6, m = idx & 63;
            float a0 = 0.f, a1 = 0.f;
#pragma unroll
            for (int n = 0; n < NORD; n += 2) {
                a0 += Esh[pl*NORD + n    ] * Wsh[(n    )*NORD + m];
                a1 += Esh[pl*NORD + n + 1] * Wsh[(n + 1)*NORD + m];
            }
            g_EWT[(size_t)m*PRED + e*45 + pl] = to_tf32(a0 + a1);
        }
        if (tid < 45) {
            float a = 0.f;
#pragma unroll
            for (int n = 0; n < NORD; n++) a += Esh[tid*NORD + n] * bsh[n];
            g_eb[e*45 + tid] = a;
        }
        return;
    }

    float* TP[6];
#pragma unroll
    for (int i = 0; i < 6; i++) TP[i] = sh + i * NORD * TSTRIDE;
    float* N0 = sh + 6 * NORD * TSTRIDE;
    float* N1 = N0 + NORD*NORD;
    __shared__ float vsh[NORD];
    __shared__ float pb[256];

    for (int i = tid; i < NORD*NORD; i += 256) N0[i] = A[i];
    __syncthreads();
    for (int i = tid; i < NORD*NORD; i += 256)
        TP[0][(i & 63)*TSTRIDE + (i >> 6)] = N0[i];
    __syncthreads();

    float* srcN = N0;
    float* dstN = N1;
    const int ig = tid >> 4;
    const int jg = tid & 15;
#pragma unroll
    for (int s = 0; s < 5; s++) {
        const float* srcT = TP[s];
        ull acc2[4][2];
#pragma unroll
        for (int ii = 0; ii < 4; ii++) { acc2[ii][0] = 0ull; acc2[ii][1] = 0ull; }
#pragma unroll 8
        for (int k = 0; k < NORD; k++) {
            const float4 a = *(const float4*)&srcT[k*TSTRIDE + ig*4];
            const ulonglong2 b = *(const ulonglong2*)&srcN[k*NORD + jg*4];
            float av[4] = {a.x, a.y, a.z, a.w};
#pragma unroll
            for (int ii = 0; ii < 4; ii++) {
                const ull am = dup2(av[ii]);
                acc2[ii][0] = fma2(am, b.x, acc2[ii][0]);
                acc2[ii][1] = fma2(am, b.y, acc2[ii][1]);
            }
        }
#pragma unroll
        for (int ii = 0; ii < 4; ii++) {
            const float2 lo = upk2(acc2[ii][0]);
            const float2 hi = upk2(acc2[ii][1]);
            float4 v; v.x = lo.x; v.y = lo.y; v.z = hi.x; v.w = hi.y;
            *(float4*)&dstN[(ig*4 + ii)*NORD + jg*4] = v;
        }
        __syncthreads();
        for (int i = tid; i < NORD*NORD; i += 256)
            TP[s+1][(i & 63)*TSTRIDE + (i >> 6)] = dstN[i];
        __syncthreads();
        float* tmp = srcN; srcN = dstN; dstN = tmp;
    }

    const int r = bid;
    const int n = tid & 63, q = tid >> 6;

    if (tid < NORD) vsh[tid] = Bv[tid];
    __syncthreads();
#pragma unroll
    for (int b = 0; b < 5; b++) {
        if ((r >> b) & 1) {
            float p = 0.f;
#pragma unroll
            for (int kk = 0; kk < 16; kk++) {
                const int k = q*16 + kk;
                p += TP[b][k*TSTRIDE + n] * vsh[k];
            }
            pb[tid] = p;
            __syncthreads();
            if (tid < NORD) vsh[tid] = pb[tid] + pb[tid+64] + pb[tid+128] + pb[tid+192];
            __syncthreads();
        }
    }

    const float* T32 = TP[5];
    float sacc = 0.f;
    for (int j = 0; j < 23; j++) {
        const int s_exp = 32*j + r;
        if (s_exp < 720 && tid < NORD) {
            const float u = vsh[tid];
            g_Kt[(719 - s_exp)*NORD + tid] = to_tf32(u);
            sacc += u;
        }
        if (j < 22) {
            float p = 0.f;
#pragma unroll
            for (int kk = 0; kk < 16; kk++) {
                const int k = q*16 + kk;
                p += T32[k*TSTRIDE + n] * vsh[k];
            }
            pb[tid] = p;
            __syncthreads();
            if (tid < NORD) vsh[tid] = pb[tid] + pb[tid+64] + pb[tid+128] + pb[tid+192];
            __syncthreads();
        }
    }
    if (tid < NORD) g_Spart[r*NORD + tid] = sacc;
}

// ============================================================================
// GEMM1 (tensor): XK[m,n] = sum_t x[m,t]*Kt[t,n] via tf32 m16n8k8 mma.
// grid (84, 15), block 128. Mtile=64, N=64, k-chunk 48. Kt arrives pre-tf32
// (float4 staging); only X needs cvt. Fused mean/var partials.
// ============================================================================
__global__ void __launch_bounds__(128) gemm1_kernel(const float* __restrict__ x) {
    __shared__ __align__(16) float Xs[TCHUNK*XSTR];   // [t][m] tf32
    __shared__ __align__(16) float Ks[TCHUNK*XSTR];   // [t][n] tf32
    __shared__ float sred[128], sqred[128];

    const int tid   = threadIdx.x;
    const int mbase = blockIdx.x * 64;
    const int h     = blockIdx.y;
    const int t0    = h * TCHUNK;

    const int ml   = tid & 63;
    const int trow = tid >> 6;           // 0/1
    const int m_load = mbase + ml;
    const int bidx   = m_load / CIN;
    const int chl    = m_load - bidx * CIN;
    const float* xrow = x + (size_t)bidx * ROW_STRIDE + chl;
    const bool mval   = (m_load < M_TOT);

    float psum = 0.f, psq = 0.f;
#pragma unroll 8
    for (int i = 0; i < TCHUNK/2; i++) {
        const int t = trow + 2*i;
        float xv = mval ? xrow[(size_t)(t0 + t) * CIN] : 0.f;
        psum += xv;
        psq  += xv * xv;
        Xs[t*XSTR + ml] = to_tf32(xv);
    }
    // Kt pre-tf32: float4 staging (6 per thread)
#pragma unroll
    for (int i = 0; i < (TCHUNK*16)/128; i++) {
        const int idx = tid + i*128;            // 0..767 float4s
        const int t = idx >> 4, n4 = idx & 15;
        *(float4*)&Ks[t*XSTR + n4*4] = *(const float4*)&g_Kt[(t0 + t)*NORD + n4*4];
    }
    __syncthreads();

    const int wid  = tid >> 5;
    const int lane = tid & 31;
    const int gid  = lane >> 2;
    const int tid4 = lane & 3;
    const int w16  = wid * 16;

    float c[8][4];
#pragma unroll
    for (int i = 0; i < 8; i++)
#pragma unroll
        for (int j = 0; j < 4; j++) c[i][j] = 0.f;

#pragma unroll
    for (int ks = 0; ks < TCHUNK/8; ks++) {
        const int kb = ks * 8;
        const int ar = (kb + tid4)*XSTR + w16 + gid;
        const uint32_t a0 = U(Xs[ar]);
        const uint32_t a1 = U(Xs[ar + 8]);
        const uint32_t a2 = U(Xs[ar + 4*XSTR]);
        const uint32_t a3 = U(Xs[ar + 4*XSTR + 8]);
#pragma unroll
        for (int ns = 0; ns < 8; ns++) {
            const int br = (kb + tid4)*XSTR + ns*8 + gid;
            const uint32_t b0 = U(Ks[br]);
            const uint32_t b1 = U(Ks[br + 4*XSTR]);
            mma_tf32(c[ns], a0, a1, a2, a3, b0, b1);
        }
    }

    float* xk = g_XK[h];
    const int row0 = mbase + w16 + gid;
#pragma unroll
    for (int ns = 0; ns < 8; ns++) {
        const int nc = ns*8 + 2*tid4;
        float2 v01; v01.x = c[ns][0]; v01.y = c[ns][1];
        float2 v23; v23.x = c[ns][2]; v23.y = c[ns][3];
        *(float2*)&xk[(size_t)row0 * NORD + nc]       = v01;
        *(float2*)&xk[(size_t)(row0+8) * NORD + nc]   = v23;
    }
    sred[tid]  = psum;
    sqred[tid] = psq;
    __syncthreads();
    if (tid < 64) {
        g_rsum[h][mbase + tid] = sred[tid] + sred[tid + 64];
        g_rsq [h][mbase + tid] = sqred[tid] + sqred[tid + 64];
    }
}

// ============================================================================
// fuse: partial reduce + stats + S + alpha/beta fold + transpose (tf32 store).
// ============================================================================
__global__ void __launch_bounds__(256) fuse_kernel(const float* __restrict__ aw,
                                                   const float* __restrict__ ab) {
    __shared__ float TT[64*65];
    __shared__ float alpha_s[64], beta_s[64], Ssh[64];
    const int tid = threadIdx.x;
    const int mb  = blockIdx.x * 64;

    if (tid < 64) {
        const int m = mb + tid;
        float s = 0.f, qq = 0.f;
#pragma unroll
        for (int h = 0; h < TSPLIT; h++) { s += g_rsum[h][m]; qq += g_rsq[h][m]; }
        const float mean = s * (1.0f / 720.0f);
        const float var  = qq * (1.0f / 720.0f) - mean * mean;
        const float sd   = sqrtf(var + 1e-5f);
        const int bidx = m / CIN;
        const int ch   = m - bidx * CIN;
        const float al = aw[ch] / sd;
        alpha_s[tid] = al;
        beta_s[tid]  = ab[ch] - mean * al;
        g_mean[m] = mean;
        g_std[m]  = sd;
    } else if (tid < 128) {
        const int nn = tid - 64;
        float s = 0.f;
#pragma unroll
        for (int rr = 0; rr < NCHAIN; rr++) s += g_Spart[rr*NORD + nn];
        Ssh[nn] = s;
    }
    __syncthreads();

#pragma unroll
    for (int i = 0; i < 16; i++) {
        const int idx = i*256 + tid;
        const int mlx = idx >> 6, nn = idx & 63;
        float v = 0.f;
#pragma unroll
        for (int h = 0; h < TSPLIT; h++) v += g_XK[h][(size_t)(mb + mlx)*NORD + nn];
        TT[nn*65 + mlx] = alpha_s[mlx]*v + beta_s[mlx]*Ssh[nn];
    }
    __syncthreads();
#pragma unroll
    for (int i = 0; i < 16; i++) {
        const int idx = i*256 + tid;
        const int nn = idx >> 6, mlx = idx & 63;
        g_XKpT[(size_t)nn*MPAD + mb + mlx] = to_tf32(TT[nn*65 + mlx]);
    }
}

// ============================================================================
// GEMM2 (tensor) + epilogue: pre[m,p] = sum_n XKpT[n,m]*EWT[n,p] + eb[p];
// out = (pre - ab)/(aw+1e-10)*sd + mean. tf32 m16n8k8 mma, K=64 resident.
// grid (84, 6), block 128. Mtile=64, Ptile=128 (Xs staged once per 128 p).
// Operands pre-tf32 -> float4 staging, no cvt. Dynamic smem 53.25 KB.
// ============================================================================
__global__ void __launch_bounds__(128) gemm2_kernel(float* __restrict__ out,
                                                    const float* __restrict__ aw,
                                                    const float* __restrict__ ab) {
    extern __shared__ float pool[];        // 4608 + 8704 = 13312 floats
    float* Xs2 = pool;                     // [n][64 m] stride 72
    float* Es  = pool + 64*XSTR;           // [n][128 p] stride 136

    const int tid   = threadIdx.x;
    const int mbase = blockIdx.x * 64;
    const int pbase = blockIdx.y * 128;

    // stage Xs2: 8 float4 per thread
#pragma unroll
    for (int i = 0; i < 8; i++) {
        const int idx = tid + i*128;            // 0..1023
        const int n = idx >> 4, mg = idx & 15;
        *(float4*)&Xs2[n*XSTR + mg*4] =
            *(const float4*)&g_XKpT[(size_t)n*MPAD + mbase + mg*4];
    }
    // stage Es: 16 float4 per thread, p guard
#pragma unroll
    for (int i = 0; i < 16; i++) {
        const int idx = tid + i*128;            // 0..2047
        const int n = idx >> 5, pg = idx & 31;
        const int p = pbase + pg*4;
        float4 v = make_float4(0.f, 0.f, 0.f, 0.f);
        if (p < PRED) v = *(const float4*)&g_EWT[(size_t)n*PRED + p];
        *(float4*)&Es[n*ESTR + pg*4] = v;
    }
    __syncthreads();

    const int wid  = tid >> 5;
    const int lane = tid & 31;
    const int gid  = lane >> 2;
    const int tid4 = lane & 3;
    const int w16  = wid * 16;

    float c[16][4];
#pragma unroll
    for (int i = 0; i < 16; i++)
#pragma unroll
        for (int j = 0; j < 4; j++) c[i][j] = 0.f;

#pragma unroll
    for (int ks = 0; ks < 8; ks++) {
        const int kb = ks * 8;
        const int ar = (kb + tid4)*XSTR + w16 + gid;
        const uint32_t a0 = U(Xs2[ar]);
        const uint32_t a1 = U(Xs2[ar + 8]);
        const uint32_t a2 = U(Xs2[ar + 4*XSTR]);
        const uint32_t a3 = U(Xs2[ar + 4*XSTR + 8]);
#pragma unroll
        for (int ps = 0; ps < 16; ps++) {
            const int br = (kb + tid4)*ESTR + ps*8 + gid;
            const uint32_t b0 = U(Es[br]);
            const uint32_t b1 = U(Es[br + 4*ESTR]);
            mma_tf32(c[ps], a0, a1, a2, a3, b0, b1);
        }
    }
    __syncthreads();   // pool reused as Os

    // epilogue: stage into Os[p_loc][m_loc] (stride 67): 128*67 = 8576 floats
    float* Os = pool;
    const int m0 = mbase + w16 + gid;
    const int m1 = m0 + 8;
    const float mean0 = g_mean[m0], sd0 = g_std[m0];
    const float mean1 = g_mean[m1], sd1 = g_std[m1];
    const int bi0 = m0 / CIN, ch0 = m0 - bi0*CIN;
    const int bi1 = m1 / CIN, ch1 = m1 - bi1*CIN;
    const float ab0 = ab[ch0], sc0 = sd0 / (aw[ch0] + 1e-10f);
    const float ab1 = ab[ch1], sc1 = sd1 / (aw[ch1] + 1e-10f);
    const int mloc0 = w16 + gid;

#pragma unroll
    for (int ps = 0; ps < 16; ps++) {
        const int pl0 = ps*8 + 2*tid4;
        const int p0  = pbase + pl0;
        const float e0 = (p0     < PRED) ? g_eb[p0]     : 0.f;
        const float e1 = (p0 + 1 < PRED) ? g_eb[p0 + 1] : 0.f;
        Os[(pl0    )*OSTR + mloc0    ] = (c[ps][0] + e0 - ab0) * sc0 + mean0;
        Os[(pl0 + 1)*OSTR + mloc0    ] = (c[ps][1] + e1 - ab0) * sc0 + mean0;
        Os[(pl0    )*OSTR + mloc0 + 8] = (c[ps][2] + e0 - ab1) * sc1 + mean1;
        Os[(pl0 + 1)*OSTR + mloc0 + 8] = (c[ps][3] + e1 - ab1) * sc1 + mean1;
    }
    __syncthreads();

    // coalesced global store: 64 lanes sweep m, two phases sweep p
    const int mls = tid & 63;
    const int ph  = tid >> 6;            // 0/1
    const int m   = mbase + mls;
    if (m < M_TOT) {
        const int bi = m / CIN;
        const int ch = m - bi * CIN;
        float* ob = out + (size_t)bi * ROW_STRIDE + ch;
        const int plim = (PRED - pbase < 128) ? (PRED - pbase) : 128;
        for (int pl = ph; pl < plim; pl += 2)
            ob[(size_t)(pbase + pl) * CIN] = Os[pl*OSTR + mls];
    }
}

// ---------------- launcher: 4 graph nodes ----------------
extern "C" void kernel_launch(void* const* d_in, const int* in_sizes, int n_in,
                              void* d_out, int out_size) {
    (void)in_sizes; (void)n_in; (void)out_size;
    const float* x  = (const float*)d_in[0];   // x_enc (16,720,321)
    const float* A  = (const float*)d_in[1];   // A (64,64)
    const float* Bv = (const float*)d_in[2];   // B_vec (64)
    const float* E  = (const float*)d_in[3];   // eval_matrix (720,64)
    const float* W  = (const float*)d_in[4];   // W_mlp (64,64)
    const float* bm = (const float*)d_in[5];   // b_mlp (64)
    const float* aw = (const float*)d_in[6];   // affine_weight (321)
    const float* ab = (const float*)d_in[7];   // affine_bias (321)
    float* out = (float*)d_out;

    const int buildk_smem = (6*NORD*TSTRIDE + 2*NORD*NORD) * (int)sizeof(float); // 137216
    cudaFuncSetAttribute(buildk_kernel, cudaFuncAttributeMaxDynamicSharedMemorySize, buildk_smem);
    const int gemm2_smem = (64*XSTR + 64*ESTR) * (int)sizeof(float);             // 53248
    cudaFuncSetAttribute(gemm2_kernel, cudaFuncAttributeMaxDynamicSharedMemorySize, gemm2_smem);

    buildk_kernel<<<NCHAIN + 16, 256, buildk_smem>>>(A, Bv, E, W, bm);
    gemm1_kernel<<<dim3(MPAD/64, TSPLIT), 128>>>(x);
    fuse_kernel<<<MPAD/64, 256>>>(aw, ab);
    gemm2_kernel<<<dim3(MPAD/64, 6), 128, gemm2_smem>>>(out, aw, ab);
}